// round 4
// baseline (speedup 1.0000x reference)
#include <cuda_runtime.h>
#include <cuda_bf16.h>
#include <cstdint>

// FlashAttentionScore B=2,N=16,S=2048,D=128 fp32 causal.
// mma.sync m16n8k16 bf16 hi/lo 3-term. BM=128, double-buffered K/V,
// fragment-unit smem layout (one LDS.128 per hi+lo fragment pair).
// out layout: [out 32*2048*128][max x8][sum x8]

#define S_LEN 2048
#define DH    128
#define BM    128
#define BN    64
#define NT    256

#define RS_QK 576      // 8 kk * 4 c * 16B = 512 + 64 pad  (576 % 128 == 64)
#define RS_V  320      // 4 kk * 4 c * 16B = 256 + 64 pad  (320 % 128 == 64)
#define SM_Q  0                         // 128*576 = 73728
#define SM_K0 73728                     // 64*576  = 36864
#define SM_K1 110592
#define SM_V0 147456                    // 128*320 = 40960
#define SM_V1 188416
#define SMEM_BYTES 229376

__device__ __forceinline__ float ex2f_(float x){
    float r; asm("ex2.approx.ftz.f32 %0, %1;" : "=f"(r) : "f"(x)); return r;
}
__device__ __forceinline__ uint32_t pk(__nv_bfloat16 a, __nv_bfloat16 b){
    return (uint32_t)__bfloat16_as_ushort(a) | ((uint32_t)__bfloat16_as_ushort(b) << 16);
}
__device__ __forceinline__ void bsplit(float x, __nv_bfloat16& h, __nv_bfloat16& lo){
    h  = __float2bfloat16_rn(x);
    lo = __float2bfloat16_rn(x - __bfloat162float(h));
}
__device__ __forceinline__ void mma16816(float c[4],
        uint32_t a0, uint32_t a1, uint32_t a2, uint32_t a3,
        uint32_t b0, uint32_t b1){
    asm volatile(
        "mma.sync.aligned.m16n8k16.row.col.f32.bf16.bf16.f32 "
        "{%0,%1,%2,%3}, {%4,%5,%6,%7}, {%8,%9}, {%0,%1,%2,%3};"
        : "+f"(c[0]), "+f"(c[1]), "+f"(c[2]), "+f"(c[3])
        : "r"(a0), "r"(a1), "r"(a2), "r"(a3), "r"(b0), "r"(b1));
}

// Q/K unit layout: addr(row,kk,c) = row*576 + kk*64 + c*16
// unit = [hi w][lo w][hi w+4][lo w+4], w = 8*kk + c   (w = bf16-pair index)
__device__ __forceinline__ void store_qk_word(char* base, int row, int w,
                                              uint32_t hi, uint32_t lo){
    char* p = base + row * RS_QK + (w >> 3) * 64 + (w & 3) * 16 + ((w & 4) << 1);
    *(uint2*)p = make_uint2(hi, lo);
}
// V^T unit layout (XOR-swizzled): row=d, word wk = key-pair index
__device__ __forceinline__ void store_v_word(char* base, int d, int wk,
                                             uint32_t hi, uint32_t lo){
    int c   = (wk & 3) ^ ((d >> 1) & 3);
    int off = (((wk >> 2) & 1) ^ ((d >> 3) & 1)) << 3;
    char* p = base + d * RS_V + (wk >> 3) * 64 + c * 16 + off;
    *(uint2*)p = make_uint2(hi, lo);
}

__device__ __forceinline__ void load_kv_tile(const float* __restrict__ Kh,
                                             const float* __restrict__ Vh,
                                             int kt, char* kb, char* vb, int t){
    // ---- K: 64 rows x 128 d, hi/lo split ----
    const float4* K4 = (const float4*)(Kh + (size_t)kt * BN * DH);
#pragma unroll
    for (int i = 0; i < 8; ++i){
        int idx = t + NT * i;
        int row = idx >> 5, c4 = idx & 31;
        float4 f = K4[idx];
        __nv_bfloat16 hx,lx,hy,ly,hz,lz,hw,lw;
        bsplit(f.x,hx,lx); bsplit(f.y,hy,ly); bsplit(f.z,hz,lz); bsplit(f.w,hw,lw);
        store_qk_word(kb, row, 2*c4,     pk(hx,hy), pk(lx,ly));
        store_qk_word(kb, row, 2*c4 + 1, pk(hz,hw), pk(lz,lw));
    }
    // ---- V transposed: thread g=t>>6 handles wk 8g..8g+7, m=t&63 -> d=2m,2m+1 ----
    const float* Vt = Vh + (size_t)kt * BN * DH;
    int g = t >> 6, m = t & 63;
#pragma unroll
    for (int i = 0; i < 8; ++i){
        int wk = 8 * g + i;
        float2 v0 = *(const float2*)(Vt + (2*wk)     * DH + 2*m);
        float2 v1 = *(const float2*)(Vt + (2*wk + 1) * DH + 2*m);
        __nv_bfloat16 h0,g0,h1,g1,h2,g2,h3,g3;
        bsplit(v0.x,h0,g0); bsplit(v1.x,h1,g1);   // d = 2m
        bsplit(v0.y,h2,g2); bsplit(v1.y,h3,g3);   // d = 2m+1
        store_v_word(vb, 2*m,     wk, pk(h0,h1), pk(g0,g1));
        store_v_word(vb, 2*m + 1, wk, pk(h2,h3), pk(g2,g3));
    }
}

__global__ void __launch_bounds__(NT, 1)
fa_mma2_kernel(const float* __restrict__ q, const float* __restrict__ k,
               const float* __restrict__ v, float* __restrict__ out,
               float* __restrict__ omax, float* __restrict__ osum)
{
    extern __shared__ char sm[];
    const int t = threadIdx.x;
    const int l = t & 31;
    const int w = t >> 5;
    const int h = blockIdx.y;
    const int qt = 15 - (int)blockIdx.x;   // big tiles first
    const int nkt = 2 * qt + 2;

    const float* Kh = k + (size_t)h * S_LEN * DH;
    const float* Vh = v + (size_t)h * S_LEN * DH;

    const float QSCALE = 0.08838834764831845f * 1.4426950408889634f; // scale*log2e

    // ---- prologue: Q -> smem (scaled, split), tile 0 -> buf0 ----
    {
        const float4* Q4 = (const float4*)(q + ((size_t)h * S_LEN + (size_t)qt * BM) * DH);
#pragma unroll
        for (int i = 0; i < 16; ++i){
            int idx = t + NT * i;
            int row = idx >> 5, c4 = idx & 31;
            float4 f = Q4[idx];
            f.x *= QSCALE; f.y *= QSCALE; f.z *= QSCALE; f.w *= QSCALE;
            __nv_bfloat16 hx,lx,hy,ly,hz,lz,hw,lw;
            bsplit(f.x,hx,lx); bsplit(f.y,hy,ly); bsplit(f.z,hz,lz); bsplit(f.w,hw,lw);
            store_qk_word(sm + SM_Q, row, 2*c4,     pk(hx,hy), pk(lx,ly));
            store_qk_word(sm + SM_Q, row, 2*c4 + 1, pk(hz,hw), pk(lz,lw));
        }
    }
    load_kv_tile(Kh, Vh, 0, sm + SM_K0, sm + SM_V0, t);
    __syncthreads();

    float o[16][4];
#pragma unroll
    for (int i = 0; i < 16; ++i){ o[i][0]=o[i][1]=o[i][2]=o[i][3]=0.f; }
    float m0=-1e30f, m1=-1e30f, l0=0.f, l1=0.f;

    // hoisted lane addresses
    const uint32_t qa = SM_Q + (uint32_t)(16*w + (l>>2)) * RS_QK + (l&3)*16;
    const uint32_t kfrag = (uint32_t)(l>>2) * RS_QK + (l&3)*16;
    const uint32_t vfrag = (uint32_t)(l>>2) * RS_V + (((l&3) ^ (l>>3)) * 16);

#pragma unroll 1
    for (int kt = 0; kt < nkt; ++kt){
        char* kb = sm + ((kt & 1) ? SM_K1 : SM_K0);
        char* vb = sm + ((kt & 1) ? SM_V1 : SM_V0);

        // ---- MMA1: S = Q K^T (3-term) ----
        float c[8][4];
#pragma unroll
        for (int i = 0; i < 8; ++i){ c[i][0]=c[i][1]=c[i][2]=c[i][3]=0.f; }
#pragma unroll
        for (int kk = 0; kk < 8; ++kk){
            uint4 A0 = *(const uint4*)(sm + qa + kk*64);
            uint4 A1 = *(const uint4*)(sm + qa + kk*64 + 8*RS_QK);
#pragma unroll
            for (int nt = 0; nt < 8; ++nt){
                uint4 B = *(const uint4*)(kb + kfrag + nt*(8*RS_QK) + kk*64);
                mma16816(c[nt], A0.x, A1.x, A0.z, A1.z, B.x, B.z);  // hh
                mma16816(c[nt], A0.y, A1.y, A0.w, A1.w, B.x, B.z);  // lh
                mma16816(c[nt], A0.x, A1.x, A0.z, A1.z, B.y, B.w);  // hl
            }
        }

        // ---- causal mask (last two k-tiles straddle the diagonal) ----
        if (kt >= nkt - 2){
            int gr0 = qt*BM + 16*w + (l>>2);
            int cb  = kt*BN + 2*(l&3);
#pragma unroll
            for (int nt = 0; nt < 8; ++nt){
                int gc = cb + 8*nt;
                if (gc   > gr0)   c[nt][0] = -1e30f;
                if (gc+1 > gr0)   c[nt][1] = -1e30f;
                if (gc   > gr0+8) c[nt][2] = -1e30f;
                if (gc+1 > gr0+8) c[nt][3] = -1e30f;
            }
        }

        // ---- online softmax (log2 domain) ----
        float tm0 = -1e30f, tm1 = -1e30f;
#pragma unroll
        for (int nt = 0; nt < 8; ++nt){
            tm0 = fmaxf(tm0, fmaxf(c[nt][0], c[nt][1]));
            tm1 = fmaxf(tm1, fmaxf(c[nt][2], c[nt][3]));
        }
        tm0 = fmaxf(tm0, __shfl_xor_sync(0xffffffffu, tm0, 1));
        tm0 = fmaxf(tm0, __shfl_xor_sync(0xffffffffu, tm0, 2));
        tm1 = fmaxf(tm1, __shfl_xor_sync(0xffffffffu, tm1, 1));
        tm1 = fmaxf(tm1, __shfl_xor_sync(0xffffffffu, tm1, 2));
        float mn0 = fmaxf(m0, tm0), mn1 = fmaxf(m1, tm1);
        float al0 = ex2f_(m0 - mn0), al1 = ex2f_(m1 - mn1);
        m0 = mn0; m1 = mn1;

        uint32_t phi[16], plo[16];
        float rs0 = 0.f, rs1 = 0.f;
#pragma unroll
        for (int nt = 0; nt < 8; ++nt){
            float p0 = ex2f_(c[nt][0]-mn0), p1 = ex2f_(c[nt][1]-mn0);
            float p2 = ex2f_(c[nt][2]-mn1), p3 = ex2f_(c[nt][3]-mn1);
            rs0 += p0 + p1; rs1 += p2 + p3;
            __nv_bfloat16 h0,g0,h1,g1,h2,g2,h3,g3;
            bsplit(p0,h0,g0); bsplit(p1,h1,g1); bsplit(p2,h2,g2); bsplit(p3,h3,g3);
            int base = (nt >> 1)*4 + (nt & 1)*2;
            phi[base]   = pk(h0,h1);  phi[base+1] = pk(h2,h3);
            plo[base]   = pk(g0,g1);  plo[base+1] = pk(g2,g3);
        }
        rs0 += __shfl_xor_sync(0xffffffffu, rs0, 1);
        rs0 += __shfl_xor_sync(0xffffffffu, rs0, 2);
        rs1 += __shfl_xor_sync(0xffffffffu, rs1, 1);
        rs1 += __shfl_xor_sync(0xffffffffu, rs1, 2);
        l0 = l0*al0 + rs0; l1 = l1*al1 + rs1;

#pragma unroll
        for (int i = 0; i < 16; ++i){
            o[i][0] *= al0; o[i][1] *= al0; o[i][2] *= al1; o[i][3] *= al1;
        }

        // ---- MMA2: O += P V (3-term) ----
#pragma unroll
        for (int kkp = 0; kkp < 4; ++kkp){
            uint32_t pa0 = phi[4*kkp], pa1 = phi[4*kkp+1], pa2 = phi[4*kkp+2], pa3 = phi[4*kkp+3];
            uint32_t pl0 = plo[4*kkp], pl1 = plo[4*kkp+1], pl2 = plo[4*kkp+2], pl3 = plo[4*kkp+3];
#pragma unroll
            for (int nt2 = 0; nt2 < 16; ++nt2){
                uint4 B = *(const uint4*)(vb + vfrag + nt2*(8*RS_V) + kkp*64);
                uint32_t b0h, b0l, b1h, b1l;
                if (nt2 & 1){ b0h = B.z; b0l = B.w; b1h = B.x; b1l = B.y; }
                else        { b0h = B.x; b0l = B.y; b1h = B.z; b1l = B.w; }
                mma16816(o[nt2], pa0,pa1,pa2,pa3, b0h,b1h);
                mma16816(o[nt2], pl0,pl1,pl2,pl3, b0h,b1h);
                mma16816(o[nt2], pa0,pa1,pa2,pa3, b0l,b1l);
            }
        }

        // ---- prefetch next tile into other buffer ----
        if (kt + 1 < nkt){
            char* kb2 = sm + ((kt & 1) ? SM_K0 : SM_K1);
            char* vb2 = sm + ((kt & 1) ? SM_V0 : SM_V1);
            load_kv_tile(Kh, Vh, kt + 1, kb2, vb2, t);
        }
        __syncthreads();
    }

    // ---- epilogue ----
    float inv0 = 1.f / l0, inv1 = 1.f / l1;
    int r0 = qt*BM + 16*w + (l>>2);
    float* po = out + ((size_t)h * S_LEN + r0) * DH + 2*(l&3);
#pragma unroll
    for (int nt2 = 0; nt2 < 16; ++nt2){
        *(float2*)(po + 8*nt2)        = make_float2(o[nt2][0]*inv0, o[nt2][1]*inv0);
        *(float2*)(po + 8*DH + 8*nt2) = make_float2(o[nt2][2]*inv1, o[nt2][3]*inv1);
    }
    if ((l & 3) == 0){
        const float LN2 = 0.6931471805599453f;
        size_t s0 = ((size_t)h * S_LEN + r0) * 8;
        size_t s1 = s0 + 64;   // row + 8
        float mn0 = m0 * LN2, mn1 = m1 * LN2;
        float4 mv0 = make_float4(mn0, mn0, mn0, mn0);
        float4 mv1 = make_float4(mn1, mn1, mn1, mn1);
        float4 lv0 = make_float4(l0, l0, l0, l0);
        float4 lv1 = make_float4(l1, l1, l1, l1);
        *(float4*)(omax + s0) = mv0; *(float4*)(omax + s0 + 4) = mv0;
        *(float4*)(omax + s1) = mv1; *(float4*)(omax + s1 + 4) = mv1;
        *(float4*)(osum + s0) = lv0; *(float4*)(osum + s0 + 4) = lv0;
        *(float4*)(osum + s1) = lv1; *(float4*)(osum + s1 + 4) = lv1;
    }
}

extern "C" void kernel_launch(void* const* d_in, const int* in_sizes, int n_in,
                              void* d_out, int out_size)
{
    const float* q = (const float*)d_in[0];
    const float* k = (const float*)d_in[1];
    const float* v = (const float*)d_in[2];

    float* out  = (float*)d_out;
    float* omax = out + (size_t)32 * 2048 * 128;
    float* osum = omax + (size_t)32 * 2048 * 8;

    cudaFuncSetAttribute(fa_mma2_kernel,
                         cudaFuncAttributeMaxDynamicSharedMemorySize, SMEM_BYTES);
    dim3 grid(16, 32);   // (q-tiles of 128 rows, heads)
    fa_mma2_kernel<<<grid, NT, SMEM_BYTES>>>(q, k, v, out, omax, osum);
}

// round 5
// speedup vs baseline: 1.2324x; 1.2324x over previous
#include <cuda_runtime.h>
#include <cuda_bf16.h>
#include <cstdint>

// FlashAttentionScore B=2,N=16,S=2048,D=128 fp32 causal.
// Two kernels: prep (fp32 -> bf16 hi/lo fragment images in gmem scratch),
// main (cp.async tile loads + mma.sync m16n8k16 bf16 3-term flash attention).
// out layout: [out 32*2048*128][max x8][sum x8]

#define S_LEN 2048
#define DH    128
#define BM    64
#define BN    64
#define NT    128
#define NHEAD 32
#define NTILE 32            // 2048/64

#define RS_QK 576           // 512B data + 64B pad per row
#define RS_V  320           // 256B data + 64B pad per row
#define QK_IMG (64*RS_QK)   // 36864 B per 64-row tile
#define V_IMG  (128*RS_V)   // 40960 B per 64-key tile

#define SM_Q  0
#define SM_K  36864
#define SM_V  73728
#define SMEM_BYTES 114688   // 2 CTAs/SM

__device__ __align__(16) char g_qimg[NHEAD * NTILE * QK_IMG];   // 37.7 MB
__device__ __align__(16) char g_kimg[NHEAD * NTILE * QK_IMG];   // 37.7 MB
__device__ __align__(16) char g_vimg[NHEAD * NTILE * V_IMG];    // 41.9 MB

__device__ __forceinline__ float ex2f_(float x){
    float r; asm("ex2.approx.ftz.f32 %0, %1;" : "=f"(r) : "f"(x)); return r;
}
__device__ __forceinline__ uint32_t pk(__nv_bfloat16 a, __nv_bfloat16 b){
    return (uint32_t)__bfloat16_as_ushort(a) | ((uint32_t)__bfloat16_as_ushort(b) << 16);
}
__device__ __forceinline__ void bsplit(float x, __nv_bfloat16& h, __nv_bfloat16& lo){
    h  = __float2bfloat16_rn(x);
    lo = __float2bfloat16_rn(x - __bfloat162float(h));
}
__device__ __forceinline__ void mma16816(float c[4],
        uint32_t a0, uint32_t a1, uint32_t a2, uint32_t a3,
        uint32_t b0, uint32_t b1){
    asm volatile(
        "mma.sync.aligned.m16n8k16.row.col.f32.bf16.bf16.f32 "
        "{%0,%1,%2,%3}, {%4,%5,%6,%7}, {%8,%9}, {%0,%1,%2,%3};"
        : "+f"(c[0]), "+f"(c[1]), "+f"(c[2]), "+f"(c[3])
        : "r"(a0), "r"(a1), "r"(a2), "r"(a3), "r"(b0), "r"(b1));
}
__device__ __forceinline__ uint32_t smem_u32(const void* p){
    uint32_t a;
    asm("{ .reg .u64 t; cvta.to.shared.u64 t, %1; cvt.u32.u64 %0, t; }" : "=r"(a) : "l"(p));
    return a;
}
__device__ __forceinline__ void cpa16(uint32_t s, const char* g){
    asm volatile("cp.async.cg.shared.global [%0], [%1], 16;" :: "r"(s), "l"(g));
}
#define CPA_COMMIT() asm volatile("cp.async.commit_group;" ::: "memory")
#define CPA_WAIT(n)  asm volatile("cp.async.wait_group %0;" :: "n"(n) : "memory")

// Q/K unit layout: addr(row,w) = row*576 + (w>>3)*64 + (w&3)*16 + ((w&4)<<1)
// 8B store {hi(w), lo(w)}; the two 8B halves of a 16B unit are w and w+4.
__device__ __forceinline__ void store_qk_word(char* base, int row, int w,
                                              uint32_t hi, uint32_t lo){
    char* p = base + row * RS_QK + (w >> 3) * 64 + (w & 3) * 16 + ((w & 4) << 1);
    *(uint2*)p = make_uint2(hi, lo);
}
// V^T unit layout (XOR-swizzled, identical to verified R4 layout)
__device__ __forceinline__ void store_v_word(char* base, int d, int wk,
                                             uint32_t hi, uint32_t lo){
    int c   = (wk & 3) ^ ((d >> 1) & 3);
    int off = (((wk >> 2) & 1) ^ ((d >> 3) & 1)) << 3;
    char* p = base + d * RS_V + (wk >> 3) * 64 + c * 16 + off;
    *(uint2*)p = make_uint2(hi, lo);
}

// ---------------- prep kernel: one block per (tile, head) ----------------
__global__ void __launch_bounds__(NT)
fa_prep_kernel(const float* __restrict__ q, const float* __restrict__ k,
               const float* __restrict__ v)
{
    const int t  = threadIdx.x;
    const int kt = blockIdx.x;     // tile 0..31
    const int h  = blockIdx.y;     // head 0..31
    const int img = h * NTILE + kt;

    const float QSCALE = 0.08838834764831845f * 1.4426950408889634f; // 1/sqrt(D)*log2e

    // ---- Q tile -> image (scaled, split) ----
    {
        const float4* Q4 = (const float4*)(q + ((size_t)h * S_LEN + (size_t)kt * BM) * DH);
        char* qb = g_qimg + (size_t)img * QK_IMG;
#pragma unroll
        for (int i = 0; i < 16; ++i){
            int idx = t + NT * i;            // row*32 + c4
            int row = idx >> 5, c4 = idx & 31;
            float4 f = Q4[idx];
            f.x *= QSCALE; f.y *= QSCALE; f.z *= QSCALE; f.w *= QSCALE;
            __nv_bfloat16 hx,lx,hy,ly,hz,lz,hw,lw;
            bsplit(f.x,hx,lx); bsplit(f.y,hy,ly); bsplit(f.z,hz,lz); bsplit(f.w,hw,lw);
            store_qk_word(qb, row, 2*c4,     pk(hx,hy), pk(lx,ly));
            store_qk_word(qb, row, 2*c4 + 1, pk(hz,hw), pk(lz,lw));
        }
    }
    // ---- K tile -> image ----
    {
        const float4* K4 = (const float4*)(k + ((size_t)h * S_LEN + (size_t)kt * BN) * DH);
        char* kb = g_kimg + (size_t)img * QK_IMG;
#pragma unroll
        for (int i = 0; i < 16; ++i){
            int idx = t + NT * i;
            int row = idx >> 5, c4 = idx & 31;
            float4 f = K4[idx];
            __nv_bfloat16 hx,lx,hy,ly,hz,lz,hw,lw;
            bsplit(f.x,hx,lx); bsplit(f.y,hy,ly); bsplit(f.z,hz,lz); bsplit(f.w,hw,lw);
            store_qk_word(kb, row, 2*c4,     pk(hx,hy), pk(lx,ly));
            store_qk_word(kb, row, 2*c4 + 1, pk(hz,hw), pk(lz,lw));
        }
    }
    // ---- V tile -> transposed image ----
    {
        const float* Vt = v + ((size_t)h * S_LEN + (size_t)kt * BN) * DH;
        char* vb = g_vimg + (size_t)img * V_IMG;
        int g = t >> 6, m = t & 63;          // g in {0,1}
#pragma unroll
        for (int i = 0; i < 16; ++i){
            int wk = 16 * g + i;             // key-pair index 0..31
            float2 v0 = *(const float2*)(Vt + (2*wk)     * DH + 2*m);
            float2 v1 = *(const float2*)(Vt + (2*wk + 1) * DH + 2*m);
            __nv_bfloat16 h0,g0,h1,g1,h2,g2,h3,g3;
            bsplit(v0.x,h0,g0); bsplit(v1.x,h1,g1);   // d = 2m
            bsplit(v0.y,h2,g2); bsplit(v1.y,h3,g3);   // d = 2m+1
            store_v_word(vb, 2*m,     wk, pk(h0,h1), pk(g0,g1));
            store_v_word(vb, 2*m + 1, wk, pk(h2,h3), pk(g2,g3));
        }
    }
}

// ---------------- main kernel ----------------
__global__ void __launch_bounds__(NT, 2)
fa_main_kernel(float* __restrict__ out, float* __restrict__ omax,
               float* __restrict__ osum)
{
    extern __shared__ char sm[];
    const int t = threadIdx.x;
    const int l = t & 31;
    const int w = t >> 5;
    const int h = blockIdx.y;
    const int qt = 31 - (int)blockIdx.x;   // big tiles first
    const int nkt = qt + 1;

    const uint32_t sb = smem_u32(sm);
    const char* gq = g_qimg + (size_t)(h * NTILE + qt) * QK_IMG;
    const char* gk = g_kimg + (size_t)h * NTILE * QK_IMG;
    const char* gv = g_vimg + (size_t)h * NTILE * V_IMG;

    // ---- prologue: Q + tile0 K,V via cp.async ----
#pragma unroll
    for (int i = 0; i < 18; ++i){
        int u = t + NT * i;
        cpa16(sb + SM_Q + u*16, gq + u*16);
    }
#pragma unroll
    for (int i = 0; i < 18; ++i){
        int u = t + NT * i;
        cpa16(sb + SM_K + u*16, gk + u*16);
    }
    CPA_COMMIT();                      // group: Q + K0
#pragma unroll
    for (int i = 0; i < 20; ++i){
        int u = t + NT * i;
        cpa16(sb + SM_V + u*16, gv + u*16);
    }
    CPA_COMMIT();                      // group: V0

    float o[16][4];
#pragma unroll
    for (int i = 0; i < 16; ++i){ o[i][0]=o[i][1]=o[i][2]=o[i][3]=0.f; }
    float m0=-1e30f, m1=-1e30f, l0=0.f, l1=0.f;

    const uint32_t qa    = SM_Q + (uint32_t)(16*w + (l>>2)) * RS_QK + (l&3)*16;
    const uint32_t kfrag = SM_K + (uint32_t)(l>>2) * RS_QK + (l&3)*16;
    const uint32_t vfrag = SM_V + (uint32_t)(l>>2) * RS_V + (((l&3) ^ (l>>3)) * 16);

#pragma unroll 1
    for (int kt = 0; kt < nkt; ++kt){
        CPA_WAIT(1);                   // K (and Q) arrived
        __syncthreads();

        // ---- MMA1: S = Q K^T (3-term) ----
        float c[8][4];
#pragma unroll
        for (int i = 0; i < 8; ++i){ c[i][0]=c[i][1]=c[i][2]=c[i][3]=0.f; }
#pragma unroll
        for (int kk = 0; kk < 8; ++kk){
            uint4 A0 = *(const uint4*)(sm + qa + kk*64);
            uint4 A1 = *(const uint4*)(sm + qa + kk*64 + 8*RS_QK);
#pragma unroll
            for (int nt = 0; nt < 8; ++nt){
                uint4 B = *(const uint4*)(sm + kfrag + nt*(8*RS_QK) + kk*64);
                mma16816(c[nt], A0.x, A1.x, A0.z, A1.z, B.x, B.z);  // hh
                mma16816(c[nt], A0.y, A1.y, A0.w, A1.w, B.x, B.z);  // lh
                mma16816(c[nt], A0.x, A1.x, A0.z, A1.z, B.y, B.w);  // hl
            }
        }

        // ---- causal mask (diagonal tile only) ----
        if (kt == qt){
            int gr0 = qt*BM + 16*w + (l>>2);
            int cb  = kt*BN + 2*(l&3);
#pragma unroll
            for (int nt = 0; nt < 8; ++nt){
                int gc = cb + 8*nt;
                if (gc   > gr0)   c[nt][0] = -1e30f;
                if (gc+1 > gr0)   c[nt][1] = -1e30f;
                if (gc   > gr0+8) c[nt][2] = -1e30f;
                if (gc+1 > gr0+8) c[nt][3] = -1e30f;
            }
        }

        // ---- online softmax (log2 domain) ----
        float tm0 = -1e30f, tm1 = -1e30f;
#pragma unroll
        for (int nt = 0; nt < 8; ++nt){
            tm0 = fmaxf(tm0, fmaxf(c[nt][0], c[nt][1]));
            tm1 = fmaxf(tm1, fmaxf(c[nt][2], c[nt][3]));
        }
        tm0 = fmaxf(tm0, __shfl_xor_sync(0xffffffffu, tm0, 1));
        tm0 = fmaxf(tm0, __shfl_xor_sync(0xffffffffu, tm0, 2));
        tm1 = fmaxf(tm1, __shfl_xor_sync(0xffffffffu, tm1, 1));
        tm1 = fmaxf(tm1, __shfl_xor_sync(0xffffffffu, tm1, 2));
        float mn0 = fmaxf(m0, tm0), mn1 = fmaxf(m1, tm1);
        float al0 = ex2f_(m0 - mn0), al1 = ex2f_(m1 - mn1);
        m0 = mn0; m1 = mn1;

        uint32_t phi[16], plo[16];
        float rs0 = 0.f, rs1 = 0.f;
#pragma unroll
        for (int nt = 0; nt < 8; ++nt){
            float p0 = ex2f_(c[nt][0]-mn0), p1 = ex2f_(c[nt][1]-mn0);
            float p2 = ex2f_(c[nt][2]-mn1), p3 = ex2f_(c[nt][3]-mn1);
            rs0 += p0 + p1; rs1 += p2 + p3;
            __nv_bfloat16 h0,g0,h1,g1,h2,g2,h3,g3;
            bsplit(p0,h0,g0); bsplit(p1,h1,g1); bsplit(p2,h2,g2); bsplit(p3,h3,g3);
            int base = (nt >> 1)*4 + (nt & 1)*2;
            phi[base]   = pk(h0,h1);  phi[base+1] = pk(h2,h3);
            plo[base]   = pk(g0,g1);  plo[base+1] = pk(g2,g3);
        }
        rs0 += __shfl_xor_sync(0xffffffffu, rs0, 1);
        rs0 += __shfl_xor_sync(0xffffffffu, rs0, 2);
        rs1 += __shfl_xor_sync(0xffffffffu, rs1, 1);
        rs1 += __shfl_xor_sync(0xffffffffu, rs1, 2);
        l0 = l0*al0 + rs0; l1 = l1*al1 + rs1;

#pragma unroll
        for (int i = 0; i < 16; ++i){
            o[i][0] *= al0; o[i][1] *= al0; o[i][2] *= al1; o[i][3] *= al1;
        }

        CPA_WAIT(0);                   // V arrived
        __syncthreads();

        // ---- MMA2: O += P V (3-term) ----
#pragma unroll
        for (int kkp = 0; kkp < 4; ++kkp){
            uint32_t pa0 = phi[4*kkp], pa1 = phi[4*kkp+1], pa2 = phi[4*kkp+2], pa3 = phi[4*kkp+3];
            uint32_t pl0 = plo[4*kkp], pl1 = plo[4*kkp+1], pl2 = plo[4*kkp+2], pl3 = plo[4*kkp+3];
#pragma unroll
            for (int nt2 = 0; nt2 < 16; ++nt2){
                uint4 B = *(const uint4*)(sm + vfrag + nt2*(8*RS_V) + kkp*64);
                uint32_t b0h, b0l, b1h, b1l;
                if (nt2 & 1){ b0h = B.z; b0l = B.w; b1h = B.x; b1l = B.y; }
                else        { b0h = B.x; b0l = B.y; b1h = B.z; b1l = B.w; }
                mma16816(o[nt2], pa0,pa1,pa2,pa3, b0h,b1h);
                mma16816(o[nt2], pl0,pl1,pl2,pl3, b0h,b1h);
                mma16816(o[nt2], pa0,pa1,pa2,pa3, b0l,b1l);
            }
        }

        __syncthreads();               // all warps done reading K/V

        if (kt + 1 < nkt){
            const char* gk2 = gk + (size_t)(kt + 1) * QK_IMG;
            const char* gv2 = gv + (size_t)(kt + 1) * V_IMG;
#pragma unroll
            for (int i = 0; i < 18; ++i){
                int u = t + NT * i;
                cpa16(sb + SM_K + u*16, gk2 + u*16);
            }
            CPA_COMMIT();
#pragma unroll
            for (int i = 0; i < 20; ++i){
                int u = t + NT * i;
                cpa16(sb + SM_V + u*16, gv2 + u*16);
            }
            CPA_COMMIT();
        }
    }

    // ---- epilogue ----
    float inv0 = 1.f / l0, inv1 = 1.f / l1;
    int r0 = qt*BM + 16*w + (l>>2);
    float* po = out + ((size_t)h * S_LEN + r0) * DH + 2*(l&3);
#pragma unroll
    for (int nt2 = 0; nt2 < 16; ++nt2){
        *(float2*)(po + 8*nt2)        = make_float2(o[nt2][0]*inv0, o[nt2][1]*inv0);
        *(float2*)(po + 8*DH + 8*nt2) = make_float2(o[nt2][2]*inv1, o[nt2][3]*inv1);
    }
    if ((l & 3) == 0){
        const float LN2 = 0.6931471805599453f;
        size_t s0 = ((size_t)h * S_LEN + r0) * 8;
        size_t s1 = s0 + 64;   // row + 8
        float mn0 = m0 * LN2, mn1 = m1 * LN2;
        float4 mv0 = make_float4(mn0, mn0, mn0, mn0);
        float4 mv1 = make_float4(mn1, mn1, mn1, mn1);
        float4 lv0 = make_float4(l0, l0, l0, l0);
        float4 lv1 = make_float4(l1, l1, l1, l1);
        *(float4*)(omax + s0) = mv0; *(float4*)(omax + s0 + 4) = mv0;
        *(float4*)(omax + s1) = mv1; *(float4*)(omax + s1 + 4) = mv1;
        *(float4*)(osum + s0) = lv0; *(float4*)(osum + s0 + 4) = lv0;
        *(float4*)(osum + s1) = lv1; *(float4*)(osum + s1 + 4) = lv1;
    }
}

extern "C" void kernel_launch(void* const* d_in, const int* in_sizes, int n_in,
                              void* d_out, int out_size)
{
    const float* q = (const float*)d_in[0];
    const float* k = (const float*)d_in[1];
    const float* v = (const float*)d_in[2];

    float* out  = (float*)d_out;
    float* omax = out + (size_t)32 * 2048 * 128;
    float* osum = omax + (size_t)32 * 2048 * 8;

    dim3 pgrid(NTILE, NHEAD);
    fa_prep_kernel<<<pgrid, NT>>>(q, k, v);

    cudaFuncSetAttribute(fa_main_kernel,
                         cudaFuncAttributeMaxDynamicSharedMemorySize, SMEM_BYTES);
    dim3 grid(NTILE, NHEAD);   // (q-tiles, heads)
    fa_main_kernel<<<grid, NT, SMEM_BYTES>>>(out, omax, osum);
}

// round 6
// speedup vs baseline: 1.2862x; 1.0437x over previous
#include <cuda_runtime.h>
#include <cuda_bf16.h>
#include <cuda_fp16.h>
#include <cstdint>

// FlashAttentionScore B=2,N=16,S=2048,D=128 fp32 causal.
// prep: K->bf16 hi/lo, V->fp16 hi/lo transposed, swizzled fragment images.
// main: cp.async + mma.sync (QK: bf16 3-term, PV: fp16 P + V hi/lo).
// out layout: [out 32*2048*128][max x8][sum x8]

#define S_LEN 2048
#define DH    128
#define BM    64
#define BN    64
#define NT    128
#define NHEAD 32
#define NTILE 32

#define K_IMG 32768          // 64 rows * 512B
#define V_IMG 32768          // 128 rows * 256B
#define SM_Q  0
#define SM_K  32768
#define SM_V  65536
#define SMEM_BYTES 98304     // 2 CTAs/SM

__device__ __align__(16) char g_kimg[NHEAD * NTILE * K_IMG];   // 33.5 MB
__device__ __align__(16) char g_vimg[NHEAD * NTILE * V_IMG];   // 33.5 MB

__device__ __forceinline__ float ex2f_(float x){
    float r; asm("ex2.approx.ftz.f32 %0, %1;" : "=f"(r) : "f"(x)); return r;
}
__device__ __forceinline__ uint32_t pk(__nv_bfloat16 a, __nv_bfloat16 b){
    return (uint32_t)__bfloat16_as_ushort(a) | ((uint32_t)__bfloat16_as_ushort(b) << 16);
}
__device__ __forceinline__ uint32_t pkh(__half a, __half b){
    return (uint32_t)__half_as_ushort(a) | ((uint32_t)__half_as_ushort(b) << 16);
}
__device__ __forceinline__ void bsplit(float x, __nv_bfloat16& h, __nv_bfloat16& lo){
    h  = __float2bfloat16_rn(x);
    lo = __float2bfloat16_rn(x - __bfloat162float(h));
}
__device__ __forceinline__ void hsplit(float x, __half& h, __half& lo){
    h  = __float2half_rn(x);
    lo = __float2half_rn(x - __half2float(h));
}
__device__ __forceinline__ void mma_bf(float c[4],
        uint32_t a0, uint32_t a1, uint32_t a2, uint32_t a3,
        uint32_t b0, uint32_t b1){
    asm volatile(
        "mma.sync.aligned.m16n8k16.row.col.f32.bf16.bf16.f32 "
        "{%0,%1,%2,%3}, {%4,%5,%6,%7}, {%8,%9}, {%0,%1,%2,%3};"
        : "+f"(c[0]), "+f"(c[1]), "+f"(c[2]), "+f"(c[3])
        : "r"(a0), "r"(a1), "r"(a2), "r"(a3), "r"(b0), "r"(b1));
}
__device__ __forceinline__ void mma_f16(float c[4],
        uint32_t a0, uint32_t a1, uint32_t a2, uint32_t a3,
        uint32_t b0, uint32_t b1){
    asm volatile(
        "mma.sync.aligned.m16n8k16.row.col.f32.f16.f16.f32 "
        "{%0,%1,%2,%3}, {%4,%5,%6,%7}, {%8,%9}, {%0,%1,%2,%3};"
        : "+f"(c[0]), "+f"(c[1]), "+f"(c[2]), "+f"(c[3])
        : "r"(a0), "r"(a1), "r"(a2), "r"(a3), "r"(b0), "r"(b1));
}
__device__ __forceinline__ uint32_t smem_u32(const void* p){
    uint32_t a;
    asm("{ .reg .u64 t; cvta.to.shared.u64 t, %1; cvt.u32.u64 %0, t; }" : "=r"(a) : "l"(p));
    return a;
}
__device__ __forceinline__ void cpa16(uint32_t s, const char* g){
    asm volatile("cp.async.cg.shared.global [%0], [%1], 16;" :: "r"(s), "l"(g));
}
#define CPA_COMMIT() asm volatile("cp.async.commit_group;" ::: "memory")
#define CPA_WAIT(n)  asm volatile("cp.async.wait_group %0;" :: "n"(n) : "memory")

// ---------------- prep: K (bf16) and V^T (fp16) swizzled images ----------------
__global__ void __launch_bounds__(NT)
fa_prep_kernel(const float* __restrict__ k, const float* __restrict__ v)
{
    const int t  = threadIdx.x;
    const int kt = blockIdx.x;
    const int h  = blockIdx.y;
    const int img = h * NTILE + kt;

    // ---- K: row=key (64), 512B/row; unit cu at ((cu^(row&7))*16) ----
    {
        const float4* K4 = (const float4*)(k + ((size_t)h * S_LEN + (size_t)kt * BN) * DH);
        char* kb = g_kimg + (size_t)img * K_IMG;
#pragma unroll
        for (int i = 0; i < 8; ++i){
            int idx = t + NT * i;              // row*16 + c4g
            int row = idx >> 4, c4g = idx & 15;
            int a = c4g >> 1, b = c4g & 1;
            int c4 = 4 * a + b;
            float4 f0 = K4[row * 32 + c4];
            float4 f1 = K4[row * 32 + c4 + 2];
            __nv_bfloat16 h0x,l0x,h0y,l0y,h0z,l0z,h0w,l0w;
            __nv_bfloat16 h1x,l1x,h1y,l1y,h1z,l1z,h1w,l1w;
            bsplit(f0.x,h0x,l0x); bsplit(f0.y,h0y,l0y); bsplit(f0.z,h0z,l0z); bsplit(f0.w,h0w,l0w);
            bsplit(f1.x,h1x,l1x); bsplit(f1.y,h1y,l1y); bsplit(f1.z,h1z,l1z); bsplit(f1.w,h1w,l1w);
            int cu0 = 4*a + 2*b, sw = row & 7;
            *(uint4*)(kb + row*512 + ((cu0   ^ sw)*16)) =
                make_uint4(pk(h0x,h0y), pk(l0x,l0y), pk(h1x,h1y), pk(l1x,l1y));
            *(uint4*)(kb + row*512 + (((cu0+1) ^ sw)*16)) =
                make_uint4(pk(h0z,h0w), pk(l0z,l0w), pk(h1z,h1w), pk(l1z,l1w));
        }
    }
    // ---- V^T: row=d (128), 256B/row, fp16 hi/lo ----
    {
        const float* Vt = v + ((size_t)h * S_LEN + (size_t)kt * BN) * DH;
        char* vb = g_vimg + (size_t)img * V_IMG;
        int g = t >> 6, m = t & 63;
#pragma unroll
        for (int i = 0; i < 8; ++i){
            int u  = 8 * g + i;                       // unit col 0..15
            int wk = ((u >> 2) << 3) + (u & 3);       // key-pair (bit2 == 0)
            float2 v0 = *(const float2*)(Vt + (2*wk)     * DH + 2*m);
            float2 v1 = *(const float2*)(Vt + (2*wk + 1) * DH + 2*m);
            float2 v2 = *(const float2*)(Vt + (2*wk + 8) * DH + 2*m);
            float2 v3 = *(const float2*)(Vt + (2*wk + 9) * DH + 2*m);
            __half a0h,a0l,a1h,a1l,a2h,a2l,a3h,a3l;
            // d = 2m
            hsplit(v0.x,a0h,a0l); hsplit(v1.x,a1h,a1l);
            hsplit(v2.x,a2h,a2l); hsplit(v3.x,a3h,a3l);
            int d0 = 2*m;
            *(uint4*)(vb + d0*256 + ((u ^ (d0 & 7))*16)) =
                make_uint4(pkh(a0h,a1h), pkh(a0l,a1l), pkh(a2h,a3h), pkh(a2l,a3l));
            // d = 2m+1
            hsplit(v0.y,a0h,a0l); hsplit(v1.y,a1h,a1l);
            hsplit(v2.y,a2h,a2l); hsplit(v3.y,a3h,a3l);
            int d1 = 2*m + 1;
            *(uint4*)(vb + d1*256 + ((u ^ (d1 & 7))*16)) =
                make_uint4(pkh(a0h,a1h), pkh(a0l,a1l), pkh(a2h,a3h), pkh(a2l,a3l));
        }
    }
}

// ---------------- main ----------------
__global__ void __launch_bounds__(NT, 2)
fa_main_kernel(const float* __restrict__ q, float* __restrict__ out,
               float* __restrict__ omax, float* __restrict__ osum)
{
    extern __shared__ char sm[];
    const int t = threadIdx.x;
    const int l = t & 31;
    const int w = t >> 5;
    const int h = blockIdx.y;
    const int qt = 31 - (int)blockIdx.x;
    const int nkt = qt + 1;

    const uint32_t sb = smem_u32(sm);
    const char* gk = g_kimg + (size_t)h * NTILE * K_IMG;
    const char* gv = g_vimg + (size_t)h * NTILE * V_IMG;

    // ---- prologue: async K0,V0; convert Q inline ----
#pragma unroll
    for (int i = 0; i < 16; ++i){
        int u = t + NT * i;
        cpa16(sb + SM_K + u*16, gk + u*16);
    }
    CPA_COMMIT();
#pragma unroll
    for (int i = 0; i < 16; ++i){
        int u = t + NT * i;
        cpa16(sb + SM_V + u*16, gv + u*16);
    }
    CPA_COMMIT();

    const float QSCALE = 0.08838834764831845f * 1.4426950408889634f; // 1/sqrt(D)*log2e
    {
        const float4* Q4 = (const float4*)(q + ((size_t)h * S_LEN + (size_t)qt * BM) * DH);
#pragma unroll
        for (int i = 0; i < 8; ++i){
            int idx = t + NT * i;
            int row = idx >> 4, c4g = idx & 15;
            int a = c4g >> 1, b = c4g & 1;
            int c4 = 4 * a + b;
            float4 f0 = Q4[row * 32 + c4];
            float4 f1 = Q4[row * 32 + c4 + 2];
            f0.x*=QSCALE; f0.y*=QSCALE; f0.z*=QSCALE; f0.w*=QSCALE;
            f1.x*=QSCALE; f1.y*=QSCALE; f1.z*=QSCALE; f1.w*=QSCALE;
            __nv_bfloat16 h0x,l0x,h0y,l0y,h0z,l0z,h0w,l0w;
            __nv_bfloat16 h1x,l1x,h1y,l1y,h1z,l1z,h1w,l1w;
            bsplit(f0.x,h0x,l0x); bsplit(f0.y,h0y,l0y); bsplit(f0.z,h0z,l0z); bsplit(f0.w,h0w,l0w);
            bsplit(f1.x,h1x,l1x); bsplit(f1.y,h1y,l1y); bsplit(f1.z,h1z,l1z); bsplit(f1.w,h1w,l1w);
            int cu0 = 4*a + 2*b, sw = row & 7;
            *(uint4*)(sm + SM_Q + row*512 + ((cu0   ^ sw)*16)) =
                make_uint4(pk(h0x,h0y), pk(l0x,l0y), pk(h1x,h1y), pk(l1x,l1y));
            *(uint4*)(sm + SM_Q + row*512 + (((cu0+1) ^ sw)*16)) =
                make_uint4(pk(h0z,h0w), pk(l0z,l0w), pk(h1z,h1w), pk(l1z,l1w));
        }
    }

    float o[16][4];
#pragma unroll
    for (int i = 0; i < 16; ++i){ o[i][0]=o[i][1]=o[i][2]=o[i][3]=0.f; }
    float m0=-1e30f, m1=-1e30f, l0=0.f, l1=0.f;

    const int r3 = l >> 2, cc = l & 3;
    const int kx = r3 >> 2;                       // flips bit0 of kk/kkp
    const uint32_t lsw = (uint32_t)(cc ^ (r3 & 3)) * 16;
    const uint32_t qbase = SM_Q + (uint32_t)(16*w + r3) * 512 + lsw;
    const uint32_t kbase = SM_K + (uint32_t)r3 * 512 + lsw;
    const uint32_t vbase = SM_V + (uint32_t)r3 * 256 + lsw;

#pragma unroll 1
    for (int kt = 0; kt < nkt; ++kt){
        CPA_WAIT(1);                   // K(kt) (and Q on kt=0) ready
        __syncthreads();

        // ---- MMA1: S = Q K^T (bf16 3-term) ----
        float c[8][4];
#pragma unroll
        for (int i = 0; i < 8; ++i){ c[i][0]=c[i][1]=c[i][2]=c[i][3]=0.f; }
#pragma unroll
        for (int kk = 0; kk < 8; ++kk){
            int ke = (kk ^ kx) * 64;
            uint4 A0 = *(const uint4*)(sm + qbase + ke);
            uint4 A1 = *(const uint4*)(sm + qbase + ke + 8*512);
#pragma unroll
            for (int nt = 0; nt < 8; ++nt){
                uint4 B = *(const uint4*)(sm + kbase + nt*4096 + ke);
                mma_bf(c[nt], A0.x, A1.x, A0.z, A1.z, B.x, B.z);  // hh
                mma_bf(c[nt], A0.y, A1.y, A0.w, A1.w, B.x, B.z);  // lh
                mma_bf(c[nt], A0.x, A1.x, A0.z, A1.z, B.y, B.w);  // hl
            }
        }

        // ---- causal mask (diagonal tile) ----
        if (kt == qt){
            int gr0 = qt*BM + 16*w + r3;
            int cb  = kt*BN + 2*cc;
#pragma unroll
            for (int nt = 0; nt < 8; ++nt){
                int gc = cb + 8*nt;
                if (gc   > gr0)   c[nt][0] = -1e30f;
                if (gc+1 > gr0)   c[nt][1] = -1e30f;
                if (gc   > gr0+8) c[nt][2] = -1e30f;
                if (gc+1 > gr0+8) c[nt][3] = -1e30f;
            }
        }

        __syncthreads();               // all warps done reading K(kt)
        if (kt + 1 < nkt){             // prefetch K(kt+1) under softmax
            const char* gk2 = gk + (size_t)(kt + 1) * K_IMG;
#pragma unroll
            for (int i = 0; i < 16; ++i){
                int u = t + NT * i;
                cpa16(sb + SM_K + u*16, gk2 + u*16);
            }
            CPA_COMMIT();
        }

        // ---- online softmax (log2 domain) ----
        float tm0 = -1e30f, tm1 = -1e30f;
#pragma unroll
        for (int nt = 0; nt < 8; ++nt){
            tm0 = fmaxf(tm0, fmaxf(c[nt][0], c[nt][1]));
            tm1 = fmaxf(tm1, fmaxf(c[nt][2], c[nt][3]));
        }
        tm0 = fmaxf(tm0, __shfl_xor_sync(0xffffffffu, tm0, 1));
        tm0 = fmaxf(tm0, __shfl_xor_sync(0xffffffffu, tm0, 2));
        tm1 = fmaxf(tm1, __shfl_xor_sync(0xffffffffu, tm1, 1));
        tm1 = fmaxf(tm1, __shfl_xor_sync(0xffffffffu, tm1, 2));
        float mn0 = fmaxf(m0, tm0), mn1 = fmaxf(m1, tm1);
        float al0 = ex2f_(m0 - mn0), al1 = ex2f_(m1 - mn1);
        m0 = mn0; m1 = mn1;

        uint32_t phi[16];
        float rs0 = 0.f, rs1 = 0.f;
#pragma unroll
        for (int nt = 0; nt < 8; ++nt){
            float p0 = ex2f_(c[nt][0]-mn0), p1 = ex2f_(c[nt][1]-mn0);
            float p2 = ex2f_(c[nt][2]-mn1), p3 = ex2f_(c[nt][3]-mn1);
            rs0 += p0 + p1; rs1 += p2 + p3;
            int base = (nt >> 1)*4 + (nt & 1)*2;
            phi[base]   = pkh(__float2half_rn(p0), __float2half_rn(p1));
            phi[base+1] = pkh(__float2half_rn(p2), __float2half_rn(p3));
        }
        rs0 += __shfl_xor_sync(0xffffffffu, rs0, 1);
        rs0 += __shfl_xor_sync(0xffffffffu, rs0, 2);
        rs1 += __shfl_xor_sync(0xffffffffu, rs1, 1);
        rs1 += __shfl_xor_sync(0xffffffffu, rs1, 2);
        l0 = l0*al0 + rs0; l1 = l1*al1 + rs1;

#pragma unroll
        for (int i = 0; i < 16; ++i){
            o[i][0] *= al0; o[i][1] *= al0; o[i][2] *= al1; o[i][3] *= al1;
        }

        CPA_WAIT(1);                   // V(kt) ready (K(kt+1) may fly)
        __syncthreads();

        // ---- MMA2: O += P V (fp16, P 1-term, V hi/lo) ----
#pragma unroll
        for (int kkp = 0; kkp < 4; ++kkp){
            uint32_t pa0 = phi[4*kkp], pa1 = phi[4*kkp+1],
                     pa2 = phi[4*kkp+2], pa3 = phi[4*kkp+3];
            int ke = (kkp ^ kx) * 64;
#pragma unroll
            for (int nt2 = 0; nt2 < 16; ++nt2){
                uint4 B = *(const uint4*)(sm + vbase + nt2*2048 + ke);
                mma_f16(o[nt2], pa0,pa1,pa2,pa3, B.x, B.z);   // P * Vhi
                mma_f16(o[nt2], pa0,pa1,pa2,pa3, B.y, B.w);   // P * Vlo
            }
        }

        __syncthreads();               // all warps done reading V(kt)
        if (kt + 1 < nkt){             // prefetch V(kt+1) under next MMA1
            const char* gv2 = gv + (size_t)(kt + 1) * V_IMG;
#pragma unroll
            for (int i = 0; i < 16; ++i){
                int u = t + NT * i;
                cpa16(sb + SM_V + u*16, gv2 + u*16);
            }
            CPA_COMMIT();
        }
    }

    // ---- epilogue ----
    float inv0 = 1.f / l0, inv1 = 1.f / l1;
    int r0 = qt*BM + 16*w + r3;
    float* po = out + ((size_t)h * S_LEN + r0) * DH + 2*cc;
#pragma unroll
    for (int nt2 = 0; nt2 < 16; ++nt2){
        *(float2*)(po + 8*nt2)        = make_float2(o[nt2][0]*inv0, o[nt2][1]*inv0);
        *(float2*)(po + 8*DH + 8*nt2) = make_float2(o[nt2][2]*inv1, o[nt2][3]*inv1);
    }
    if (cc == 0){
        const float LN2 = 0.6931471805599453f;
        size_t s0 = ((size_t)h * S_LEN + r0) * 8;
        size_t s1 = s0 + 64;
        float mn0 = m0 * LN2, mn1 = m1 * LN2;
        float4 mv0 = make_float4(mn0, mn0, mn0, mn0);
        float4 mv1 = make_float4(mn1, mn1, mn1, mn1);
        float4 lv0 = make_float4(l0, l0, l0, l0);
        float4 lv1 = make_float4(l1, l1, l1, l1);
        *(float4*)(omax + s0) = mv0; *(float4*)(omax + s0 + 4) = mv0;
        *(float4*)(omax + s1) = mv1; *(float4*)(omax + s1 + 4) = mv1;
        *(float4*)(osum + s0) = lv0; *(float4*)(osum + s0 + 4) = lv0;
        *(float4*)(osum + s1) = lv1; *(float4*)(osum + s1 + 4) = lv1;
    }
}

extern "C" void kernel_launch(void* const* d_in, const int* in_sizes, int n_in,
                              void* d_out, int out_size)
{
    const float* q = (const float*)d_in[0];
    const float* k = (const float*)d_in[1];
    const float* v = (const float*)d_in[2];

    float* out  = (float*)d_out;
    float* omax = out + (size_t)32 * 2048 * 128;
    float* osum = omax + (size_t)32 * 2048 * 8;

    dim3 pgrid(NTILE, NHEAD);
    fa_prep_kernel<<<pgrid, NT>>>(k, v);

    cudaFuncSetAttribute(fa_main_kernel,
                         cudaFuncAttributeMaxDynamicSharedMemorySize, SMEM_BYTES);
    dim3 grid(NTILE, NHEAD);
    fa_main_kernel<<<grid, NT, SMEM_BYTES>>>(q, out, omax, osum);
}

// round 7
// speedup vs baseline: 1.4307x; 1.1124x over previous
#include <cuda_runtime.h>
#include <cuda_bf16.h>
#include <cuda_fp16.h>
#include <cstdint>

// FlashAttentionScore B=2,N=16,S=2048,D=128 fp32 causal.
// prep: K->bf16 hi/lo, V->fp16 hi/lo transposed fragment images (padded rows).
// main: cp.async early-prefetch + mma.sync (QK bf16 3-term, PV fp16 P + Vhi/Vlo).
// out layout: [out 32*2048*128][max x8][sum x8]

#define S_LEN 2048
#define DH    128
#define BM    64
#define BN    64
#define NT    128
#define NHEAD 32
#define NTILE 32

#define RS_QK 576           // 512B data + 64B pad per row  (verified conflict profile)
#define RS_V  320           // 256B data + 64B pad per row
#define K_IMG (64*RS_QK)    // 36864
#define V_IMG (128*RS_V)    // 40960

#define SM_Q  0
#define SM_K  36864
#define SM_V  73728
#define SMEM_BYTES 114688   // 2 CTAs/SM

__device__ __align__(16) char g_kimg[NHEAD * NTILE * K_IMG];   // 37.7 MB
__device__ __align__(16) char g_vimg[NHEAD * NTILE * V_IMG];   // 41.9 MB

__device__ __forceinline__ float ex2f_(float x){
    float r; asm("ex2.approx.ftz.f32 %0, %1;" : "=f"(r) : "f"(x)); return r;
}
__device__ __forceinline__ uint32_t pk(__nv_bfloat16 a, __nv_bfloat16 b){
    return (uint32_t)__bfloat16_as_ushort(a) | ((uint32_t)__bfloat16_as_ushort(b) << 16);
}
__device__ __forceinline__ uint32_t pkh(__half a, __half b){
    return (uint32_t)__half_as_ushort(a) | ((uint32_t)__half_as_ushort(b) << 16);
}
__device__ __forceinline__ void bsplit(float x, __nv_bfloat16& h, __nv_bfloat16& lo){
    h  = __float2bfloat16_rn(x);
    lo = __float2bfloat16_rn(x - __bfloat162float(h));
}
__device__ __forceinline__ void hsplit(float x, __half& h, __half& lo){
    h  = __float2half_rn(x);
    lo = __float2half_rn(x - __half2float(h));
}
__device__ __forceinline__ void mma_bf(float c[4],
        uint32_t a0, uint32_t a1, uint32_t a2, uint32_t a3,
        uint32_t b0, uint32_t b1){
    asm volatile(
        "mma.sync.aligned.m16n8k16.row.col.f32.bf16.bf16.f32 "
        "{%0,%1,%2,%3}, {%4,%5,%6,%7}, {%8,%9}, {%0,%1,%2,%3};"
        : "+f"(c[0]), "+f"(c[1]), "+f"(c[2]), "+f"(c[3])
        : "r"(a0), "r"(a1), "r"(a2), "r"(a3), "r"(b0), "r"(b1));
}
__device__ __forceinline__ void mma_f16(float c[4],
        uint32_t a0, uint32_t a1, uint32_t a2, uint32_t a3,
        uint32_t b0, uint32_t b1){
    asm volatile(
        "mma.sync.aligned.m16n8k16.row.col.f32.f16.f16.f32 "
        "{%0,%1,%2,%3}, {%4,%5,%6,%7}, {%8,%9}, {%0,%1,%2,%3};"
        : "+f"(c[0]), "+f"(c[1]), "+f"(c[2]), "+f"(c[3])
        : "r"(a0), "r"(a1), "r"(a2), "r"(a3), "r"(b0), "r"(b1));
}
__device__ __forceinline__ uint32_t smem_u32(const void* p){
    uint32_t a;
    asm("{ .reg .u64 t; cvta.to.shared.u64 t, %1; cvt.u32.u64 %0, t; }" : "=r"(a) : "l"(p));
    return a;
}
__device__ __forceinline__ void cpa16(uint32_t s, const char* g){
    asm volatile("cp.async.cg.shared.global [%0], [%1], 16;" :: "r"(s), "l"(g));
}
#define CPA_COMMIT() asm volatile("cp.async.commit_group;" ::: "memory")
#define CPA_WAIT(n)  asm volatile("cp.async.wait_group %0;" :: "n"(n) : "memory")

// Q/K unit layout (R4/R5-verified): addr(row,w) = row*576 + (w>>3)*64 + (w&3)*16 + ((w&4)<<1)
__device__ __forceinline__ void store_qk_word(char* base, int row, int w,
                                              uint32_t hi, uint32_t lo){
    char* p = base + row * RS_QK + (w >> 3) * 64 + (w & 3) * 16 + ((w & 4) << 1);
    *(uint2*)p = make_uint2(hi, lo);
}
// V^T unit layout (R4/R5-verified XOR swizzle): row=d, wk = key-pair index
__device__ __forceinline__ void store_v_word(char* base, int d, int wk,
                                             uint32_t hi, uint32_t lo){
    int c   = (wk & 3) ^ ((d >> 1) & 3);
    int off = (((wk >> 2) & 1) ^ ((d >> 3) & 1)) << 3;
    char* p = base + d * RS_V + (wk >> 3) * 64 + c * 16 + off;
    *(uint2*)p = make_uint2(hi, lo);
}

// ---------------- prep: K (bf16 hi/lo) and V^T (fp16 hi/lo) images ----------------
__global__ void __launch_bounds__(NT)
fa_prep_kernel(const float* __restrict__ k, const float* __restrict__ v)
{
    const int t  = threadIdx.x;
    const int kt = blockIdx.x;
    const int h  = blockIdx.y;
    const int img = h * NTILE + kt;

    // ---- K tile -> image ----
    {
        const float4* K4 = (const float4*)(k + ((size_t)h * S_LEN + (size_t)kt * BN) * DH);
        char* kb = g_kimg + (size_t)img * K_IMG;
#pragma unroll
        for (int i = 0; i < 16; ++i){
            int idx = t + NT * i;            // row*32 + c4
            int row = idx >> 5, c4 = idx & 31;
            float4 f = K4[idx];
            __nv_bfloat16 hx,lx,hy,ly,hz,lz,hw,lw;
            bsplit(f.x,hx,lx); bsplit(f.y,hy,ly); bsplit(f.z,hz,lz); bsplit(f.w,hw,lw);
            store_qk_word(kb, row, 2*c4,     pk(hx,hy), pk(lx,ly));
            store_qk_word(kb, row, 2*c4 + 1, pk(hz,hw), pk(lz,lw));
        }
    }
    // ---- V tile -> transposed fp16 image ----
    {
        const float* Vt = v + ((size_t)h * S_LEN + (size_t)kt * BN) * DH;
        char* vb = g_vimg + (size_t)img * V_IMG;
        int g = t >> 6, m = t & 63;          // g in {0,1}
#pragma unroll
        for (int i = 0; i < 16; ++i){
            int wk = 16 * g + i;             // key-pair index 0..31
            float2 v0 = *(const float2*)(Vt + (2*wk)     * DH + 2*m);
            float2 v1 = *(const float2*)(Vt + (2*wk + 1) * DH + 2*m);
            __half h0,g0,h1,g1,h2,g2,h3,g3;
            hsplit(v0.x,h0,g0); hsplit(v1.x,h1,g1);   // d = 2m
            hsplit(v0.y,h2,g2); hsplit(v1.y,h3,g3);   // d = 2m+1
            store_v_word(vb, 2*m,     wk, pkh(h0,h1), pkh(g0,g1));
            store_v_word(vb, 2*m + 1, wk, pkh(h2,h3), pkh(g2,g3));
        }
    }
}

// ---------------- main ----------------
__global__ void __launch_bounds__(NT, 2)
fa_main_kernel(const float* __restrict__ q, float* __restrict__ out,
               float* __restrict__ omax, float* __restrict__ osum)
{
    extern __shared__ char sm[];
    const int t = threadIdx.x;
    const int l = t & 31;
    const int w = t >> 5;
    const int h = blockIdx.y;
    const int qt = 31 - (int)blockIdx.x;   // big tiles first
    const int nkt = qt + 1;

    const uint32_t sb = smem_u32(sm);
    const char* gk = g_kimg + (size_t)h * NTILE * K_IMG;
    const char* gv = g_vimg + (size_t)h * NTILE * V_IMG;

    // ---- prologue: async K0,V0; Q converted inline into smem ----
#pragma unroll
    for (int i = 0; i < 18; ++i){
        int u = t + NT * i;
        cpa16(sb + SM_K + u*16, gk + u*16);
    }
    CPA_COMMIT();                      // group: K0
#pragma unroll
    for (int i = 0; i < 20; ++i){
        int u = t + NT * i;
        cpa16(sb + SM_V + u*16, gv + u*16);
    }
    CPA_COMMIT();                      // group: V0

    const float QSCALE = 0.08838834764831845f * 1.4426950408889634f; // 1/sqrt(D)*log2e
    {
        const float4* Q4 = (const float4*)(q + ((size_t)h * S_LEN + (size_t)qt * BM) * DH);
#pragma unroll
        for (int i = 0; i < 16; ++i){
            int idx = t + NT * i;
            int row = idx >> 5, c4 = idx & 31;
            float4 f = Q4[idx];
            f.x *= QSCALE; f.y *= QSCALE; f.z *= QSCALE; f.w *= QSCALE;
            __nv_bfloat16 hx,lx,hy,ly,hz,lz,hw,lw;
            bsplit(f.x,hx,lx); bsplit(f.y,hy,ly); bsplit(f.z,hz,lz); bsplit(f.w,hw,lw);
            store_qk_word(sm + SM_Q, row, 2*c4,     pk(hx,hy), pk(lx,ly));
            store_qk_word(sm + SM_Q, row, 2*c4 + 1, pk(hz,hw), pk(lz,lw));
        }
    }

    float o[16][4];
#pragma unroll
    for (int i = 0; i < 16; ++i){ o[i][0]=o[i][1]=o[i][2]=o[i][3]=0.f; }
    float m0=-1e30f, m1=-1e30f, l0=0.f, l1=0.f;

    const int r3 = l >> 2, cc = l & 3;
    const uint32_t qa    = SM_Q + (uint32_t)(16*w + r3) * RS_QK + cc*16;
    const uint32_t kfrag = SM_K + (uint32_t)r3 * RS_QK + cc*16;
    const uint32_t vfrag = SM_V + (uint32_t)r3 * RS_V + (((cc) ^ (l>>3)) * 16);

#pragma unroll 1
    for (int kt = 0; kt < nkt; ++kt){
        CPA_WAIT(1);                   // K(kt) ready (V(kt) may still fly)
        __syncthreads();

        // ---- MMA1: S = Q K^T (bf16 3-term) ----
        float c[8][4];
#pragma unroll
        for (int i = 0; i < 8; ++i){ c[i][0]=c[i][1]=c[i][2]=c[i][3]=0.f; }
#pragma unroll
        for (int kk = 0; kk < 8; ++kk){
            uint4 A0 = *(const uint4*)(sm + qa + kk*64);
            uint4 A1 = *(const uint4*)(sm + qa + kk*64 + 8*RS_QK);
#pragma unroll
            for (int nt = 0; nt < 8; ++nt){
                uint4 B = *(const uint4*)(sm + kfrag + nt*(8*RS_QK) + kk*64);
                mma_bf(c[nt], A0.x, A1.x, A0.z, A1.z, B.x, B.z);  // hh
                mma_bf(c[nt], A0.y, A1.y, A0.w, A1.w, B.x, B.z);  // lh
                mma_bf(c[nt], A0.x, A1.x, A0.z, A1.z, B.y, B.w);  // hl
            }
        }

        // ---- causal mask (diagonal tile only) ----
        if (kt == qt){
            int gr0 = qt*BM + 16*w + r3;
            int cb  = kt*BN + 2*cc;
#pragma unroll
            for (int nt = 0; nt < 8; ++nt){
                int gc = cb + 8*nt;
                if (gc   > gr0)   c[nt][0] = -1e30f;
                if (gc+1 > gr0)   c[nt][1] = -1e30f;
                if (gc   > gr0+8) c[nt][2] = -1e30f;
                if (gc+1 > gr0+8) c[nt][3] = -1e30f;
            }
        }

        __syncthreads();               // all warps done reading K(kt)
        if (kt + 1 < nkt){             // prefetch K(kt+1): hides under softmax+MMA2
            const char* gk2 = gk + (size_t)(kt + 1) * K_IMG;
#pragma unroll
            for (int i = 0; i < 18; ++i){
                int u = t + NT * i;
                cpa16(sb + SM_K + u*16, gk2 + u*16);
            }
            CPA_COMMIT();
        }

        // ---- online softmax (log2 domain) ----
        float tm0 = -1e30f, tm1 = -1e30f;
#pragma unroll
        for (int nt = 0; nt < 8; ++nt){
            tm0 = fmaxf(tm0, fmaxf(c[nt][0], c[nt][1]));
            tm1 = fmaxf(tm1, fmaxf(c[nt][2], c[nt][3]));
        }
        tm0 = fmaxf(tm0, __shfl_xor_sync(0xffffffffu, tm0, 1));
        tm0 = fmaxf(tm0, __shfl_xor_sync(0xffffffffu, tm0, 2));
        tm1 = fmaxf(tm1, __shfl_xor_sync(0xffffffffu, tm1, 1));
        tm1 = fmaxf(tm1, __shfl_xor_sync(0xffffffffu, tm1, 2));
        float mn0 = fmaxf(m0, tm0), mn1 = fmaxf(m1, tm1);
        float al0 = ex2f_(m0 - mn0), al1 = ex2f_(m1 - mn1);
        m0 = mn0; m1 = mn1;

        uint32_t phi[16];
        float rs0 = 0.f, rs1 = 0.f;
#pragma unroll
        for (int nt = 0; nt < 8; ++nt){
            float p0 = ex2f_(c[nt][0]-mn0), p1 = ex2f_(c[nt][1]-mn0);
            float p2 = ex2f_(c[nt][2]-mn1), p3 = ex2f_(c[nt][3]-mn1);
            rs0 += p0 + p1; rs1 += p2 + p3;
            int base = (nt >> 1)*4 + (nt & 1)*2;
            phi[base]   = pkh(__float2half_rn(p0), __float2half_rn(p1));
            phi[base+1] = pkh(__float2half_rn(p2), __float2half_rn(p3));
        }
        rs0 += __shfl_xor_sync(0xffffffffu, rs0, 1);
        rs0 += __shfl_xor_sync(0xffffffffu, rs0, 2);
        rs1 += __shfl_xor_sync(0xffffffffu, rs1, 1);
        rs1 += __shfl_xor_sync(0xffffffffu, rs1, 2);
        l0 = l0*al0 + rs0; l1 = l1*al1 + rs1;

#pragma unroll
        for (int i = 0; i < 16; ++i){
            o[i][0] *= al0; o[i][1] *= al0; o[i][2] *= al1; o[i][3] *= al1;
        }

        CPA_WAIT(1);                   // V(kt) ready (K(kt+1) may fly)
        __syncthreads();

        // ---- MMA2: O += P V (fp16; P 1-term, V hi/lo) ----
#pragma unroll
        for (int kkp = 0; kkp < 4; ++kkp){
            uint32_t pa0 = phi[4*kkp], pa1 = phi[4*kkp+1],
                     pa2 = phi[4*kkp+2], pa3 = phi[4*kkp+3];
#pragma unroll
            for (int nt2 = 0; nt2 < 16; ++nt2){
                uint4 B = *(const uint4*)(sm + vfrag + nt2*(8*RS_V) + kkp*64);
                uint32_t b0h, b0l, b1h, b1l;
                if (nt2 & 1){ b0h = B.z; b0l = B.w; b1h = B.x; b1l = B.y; }
                else        { b0h = B.x; b0l = B.y; b1h = B.z; b1l = B.w; }
                mma_f16(o[nt2], pa0,pa1,pa2,pa3, b0h, b1h);   // P * Vhi
                mma_f16(o[nt2], pa0,pa1,pa2,pa3, b0l, b1l);   // P * Vlo
            }
        }

        __syncthreads();               // all warps done reading V(kt)
        if (kt + 1 < nkt){             // prefetch V(kt+1): hides under next MMA1
            const char* gv2 = gv + (size_t)(kt + 1) * V_IMG;
#pragma unroll
            for (int i = 0; i < 20; ++i){
                int u = t + NT * i;
                cpa16(sb + SM_V + u*16, gv2 + u*16);
            }
            CPA_COMMIT();
        }
    }

    // ---- epilogue ----
    float inv0 = 1.f / l0, inv1 = 1.f / l1;
    int r0 = qt*BM + 16*w + r3;
    float* po = out + ((size_t)h * S_LEN + r0) * DH + 2*cc;
#pragma unroll
    for (int nt2 = 0; nt2 < 16; ++nt2){
        *(float2*)(po + 8*nt2)        = make_float2(o[nt2][0]*inv0, o[nt2][1]*inv0);
        *(float2*)(po + 8*DH + 8*nt2) = make_float2(o[nt2][2]*inv1, o[nt2][3]*inv1);
    }
    if (cc == 0){
        const float LN2 = 0.6931471805599453f;
        size_t s0 = ((size_t)h * S_LEN + r0) * 8;
        size_t s1 = s0 + 64;   // row + 8
        float mn0 = m0 * LN2, mn1 = m1 * LN2;
        float4 mv0 = make_float4(mn0, mn0, mn0, mn0);
        float4 mv1 = make_float4(mn1, mn1, mn1, mn1);
        float4 lv0 = make_float4(l0, l0, l0, l0);
        float4 lv1 = make_float4(l1, l1, l1, l1);
        *(float4*)(omax + s0) = mv0; *(float4*)(omax + s0 + 4) = mv0;
        *(float4*)(omax + s1) = mv1; *(float4*)(omax + s1 + 4) = mv1;
        *(float4*)(osum + s0) = lv0; *(float4*)(osum + s0 + 4) = lv0;
        *(float4*)(osum + s1) = lv1; *(float4*)(osum + s1 + 4) = lv1;
    }
}

extern "C" void kernel_launch(void* const* d_in, const int* in_sizes, int n_in,
                              void* d_out, int out_size)
{
    const float* q = (const float*)d_in[0];
    const float* k = (const float*)d_in[1];
    const float* v = (const float*)d_in[2];

    float* out  = (float*)d_out;
    float* omax = out + (size_t)32 * 2048 * 128;
    float* osum = omax + (size_t)32 * 2048 * 8;

    dim3 pgrid(NTILE, NHEAD);
    fa_prep_kernel<<<pgrid, NT>>>(k, v);

    cudaFuncSetAttribute(fa_main_kernel,
                         cudaFuncAttributeMaxDynamicSharedMemorySize, SMEM_BYTES);
    dim3 grid(NTILE, NHEAD);
    fa_main_kernel<<<grid, NT, SMEM_BYTES>>>(q, out, omax, osum);
}

// round 8
// speedup vs baseline: 1.9114x; 1.3360x over previous
#include <cuda_runtime.h>
#include <cuda_fp16.h>
#include <cstdint>

// FlashAttentionScore B=2,N=16,S=2048,D=128 fp32 causal.
// prep: K->fp16 (single), V->fp16 hi/lo transposed fragment images.
// main: cp.async early-prefetch + mma.sync fp16 (QK 1-term, PV P*Vhi+P*Vlo).
// out layout: [out 32*2048*128][max x8][sum x8]

#define S_LEN 2048
#define DH    128
#define BM    64
#define BN    64
#define NT    128
#define NHEAD 32
#define NTILE 32

#define RS_QK 272           // 256B data + 16B pad (row stride ≡16 mod 128: even 2-phase LDS.64)
#define RS_V  320           // 256B data + 64B pad (R5/R7-verified)
#define K_IMG (64*RS_QK)    // 17408
#define V_IMG (128*RS_V)    // 40960
#define K_UNITS (K_IMG/16)  // 1088

#define SM_Q  0
#define SM_K  17408
#define SM_V  34816
#define SMEM_BYTES 75776    // 2 CTAs/SM

__device__ __align__(16) char g_kimg[NHEAD * NTILE * K_IMG];   // 17.8 MB
__device__ __align__(16) char g_vimg[NHEAD * NTILE * V_IMG];   // 41.9 MB

__device__ __forceinline__ float ex2f_(float x){
    float r; asm("ex2.approx.ftz.f32 %0, %1;" : "=f"(r) : "f"(x)); return r;
}
__device__ __forceinline__ uint32_t pkh(__half a, __half b){
    return (uint32_t)__half_as_ushort(a) | ((uint32_t)__half_as_ushort(b) << 16);
}
__device__ __forceinline__ void hsplit(float x, __half& h, __half& lo){
    h  = __float2half_rn(x);
    lo = __float2half_rn(x - __half2float(h));
}
__device__ __forceinline__ void mma_f16(float c[4],
        uint32_t a0, uint32_t a1, uint32_t a2, uint32_t a3,
        uint32_t b0, uint32_t b1){
    asm volatile(
        "mma.sync.aligned.m16n8k16.row.col.f32.f16.f16.f32 "
        "{%0,%1,%2,%3}, {%4,%5,%6,%7}, {%8,%9}, {%0,%1,%2,%3};"
        : "+f"(c[0]), "+f"(c[1]), "+f"(c[2]), "+f"(c[3])
        : "r"(a0), "r"(a1), "r"(a2), "r"(a3), "r"(b0), "r"(b1));
}
__device__ __forceinline__ uint32_t smem_u32(const void* p){
    uint32_t a;
    asm("{ .reg .u64 t; cvta.to.shared.u64 t, %1; cvt.u32.u64 %0, t; }" : "=r"(a) : "l"(p));
    return a;
}
__device__ __forceinline__ void cpa16(uint32_t s, const char* g){
    asm volatile("cp.async.cg.shared.global [%0], [%1], 16;" :: "r"(s), "l"(g));
}
#define CPA_COMMIT() asm volatile("cp.async.commit_group;" ::: "memory")
#define CPA_WAIT(n)  asm volatile("cp.async.wait_group %0;" :: "n"(n) : "memory")

// Q/K fp16 unit: addr(row,kk,c) = row*272 + kk*32 + c*8
//   8B = [pair(8kk+c), pair(8kk+4+c)]  (pair w = d elements {2w,2w+1})
// V^T unit (verified): row=d, wk = key-pair index, hi/lo interleaved
__device__ __forceinline__ void store_v_word(char* base, int d, int wk,
                                             uint32_t hi, uint32_t lo){
    int c   = (wk & 3) ^ ((d >> 1) & 3);
    int off = (((wk >> 2) & 1) ^ ((d >> 3) & 1)) << 3;
    char* p = base + d * RS_V + (wk >> 3) * 64 + c * 16 + off;
    *(uint2*)p = make_uint2(hi, lo);
}

// ---------------- prep: K (fp16 single) and V^T (fp16 hi/lo) images ----------------
__global__ void __launch_bounds__(NT)
fa_prep_kernel(const float* __restrict__ k, const float* __restrict__ v)
{
    const int t  = threadIdx.x;
    const int kt = blockIdx.x;
    const int h  = blockIdx.y;
    const int img = h * NTILE + kt;

    // ---- K tile -> fp16 image ----
    {
        const float* Kt = k + ((size_t)h * S_LEN + (size_t)kt * BN) * DH;
        char* kb = g_kimg + (size_t)img * K_IMG;
#pragma unroll
        for (int i = 0; i < 16; ++i){
            int idx = t + NT * i;            // row*32 + kk*4 + c
            int row = idx >> 5, kc = idx & 31;
            int kk = kc >> 2, c = kc & 3;
            int d0 = 16*kk + 2*c;
            float2 v0 = *(const float2*)(Kt + row * DH + d0);
            float2 v1 = *(const float2*)(Kt + row * DH + d0 + 8);
            uint2 u = make_uint2(pkh(__float2half_rn(v0.x), __float2half_rn(v0.y)),
                                 pkh(__float2half_rn(v1.x), __float2half_rn(v1.y)));
            *(uint2*)(kb + row * RS_QK + kk * 32 + c * 8) = u;
        }
    }
    // ---- V tile -> transposed fp16 hi/lo image ----
    {
        const float* Vt = v + ((size_t)h * S_LEN + (size_t)kt * BN) * DH;
        char* vb = g_vimg + (size_t)img * V_IMG;
        int g = t >> 6, m = t & 63;
#pragma unroll
        for (int i = 0; i < 16; ++i){
            int wk = 16 * g + i;             // key-pair 0..31
            float2 v0 = *(const float2*)(Vt + (2*wk)     * DH + 2*m);
            float2 v1 = *(const float2*)(Vt + (2*wk + 1) * DH + 2*m);
            __half h0,g0,h1,g1,h2,g2,h3,g3;
            hsplit(v0.x,h0,g0); hsplit(v1.x,h1,g1);   // d = 2m
            hsplit(v0.y,h2,g2); hsplit(v1.y,h3,g3);   // d = 2m+1
            store_v_word(vb, 2*m,     wk, pkh(h0,h1), pkh(g0,g1));
            store_v_word(vb, 2*m + 1, wk, pkh(h2,h3), pkh(g2,g3));
        }
    }
}

// ---------------- main ----------------
__global__ void __launch_bounds__(NT, 2)
fa_main_kernel(const float* __restrict__ q, float* __restrict__ out,
               float* __restrict__ omax, float* __restrict__ osum)
{
    extern __shared__ char sm[];
    const int t = threadIdx.x;
    const int l = t & 31;
    const int w = t >> 5;
    const int h = blockIdx.y;
    const int qt = 31 - (int)blockIdx.x;   // big tiles first
    const int nkt = qt + 1;

    const uint32_t sb = smem_u32(sm);
    const char* gk = g_kimg + (size_t)h * NTILE * K_IMG;
    const char* gv = g_vimg + (size_t)h * NTILE * V_IMG;

    // ---- prologue: async K0,V0; Q converted inline ----
#pragma unroll
    for (int i = 0; i < 9; ++i){
        int u = t + NT * i;
        if (u < K_UNITS) cpa16(sb + SM_K + u*16, gk + u*16);
    }
    CPA_COMMIT();                      // group: K0
#pragma unroll
    for (int i = 0; i < 20; ++i){
        int u = t + NT * i;
        cpa16(sb + SM_V + u*16, gv + u*16);
    }
    CPA_COMMIT();                      // group: V0

    const float QSCALE = 0.08838834764831845f * 1.4426950408889634f; // 1/sqrt(D)*log2e
    {
        const float* Qt = q + ((size_t)h * S_LEN + (size_t)qt * BM) * DH;
#pragma unroll
        for (int i = 0; i < 16; ++i){
            int idx = t + NT * i;
            int row = idx >> 5, kc = idx & 31;
            int kk = kc >> 2, c = kc & 3;
            int d0 = 16*kk + 2*c;
            float2 v0 = *(const float2*)(Qt + row * DH + d0);
            float2 v1 = *(const float2*)(Qt + row * DH + d0 + 8);
            uint2 u = make_uint2(pkh(__float2half_rn(v0.x * QSCALE),
                                     __float2half_rn(v0.y * QSCALE)),
                                 pkh(__float2half_rn(v1.x * QSCALE),
                                     __float2half_rn(v1.y * QSCALE)));
            *(uint2*)(sm + SM_Q + row * RS_QK + kk * 32 + c * 8) = u;
        }
    }

    float o[16][4];
#pragma unroll
    for (int i = 0; i < 16; ++i){ o[i][0]=o[i][1]=o[i][2]=o[i][3]=0.f; }
    float m0=-1e30f, m1=-1e30f, l0=0.f, l1=0.f;

    const int r3 = l >> 2, cc = l & 3;
    const uint32_t qa    = SM_Q + (uint32_t)(16*w + r3) * RS_QK + cc*8;
    const uint32_t kfrag = SM_K + (uint32_t)r3 * RS_QK + cc*8;
    const uint32_t vfrag = SM_V + (uint32_t)r3 * RS_V + ((cc ^ (l>>3)) * 16);

#pragma unroll 1
    for (int kt = 0; kt < nkt; ++kt){
        CPA_WAIT(1);                   // K(kt) ready
        __syncthreads();

        // ---- MMA1: S = Q K^T (fp16 1-term) ----
        float c[8][4];
#pragma unroll
        for (int i = 0; i < 8; ++i){ c[i][0]=c[i][1]=c[i][2]=c[i][3]=0.f; }
#pragma unroll
        for (int kk = 0; kk < 8; ++kk){
            uint2 A0 = *(const uint2*)(sm + qa + kk*32);             // row r:   {a0,a2}
            uint2 A1 = *(const uint2*)(sm + qa + kk*32 + 8*RS_QK);   // row r+8: {a1,a3}
#pragma unroll
            for (int nt = 0; nt < 8; ++nt){
                uint2 B = *(const uint2*)(sm + kfrag + nt*(8*RS_QK) + kk*32);
                mma_f16(c[nt], A0.x, A1.x, A0.y, A1.y, B.x, B.y);
            }
        }

        // ---- causal mask (diagonal tile only) ----
        if (kt == qt){
            int gr0 = qt*BM + 16*w + r3;
            int cb  = kt*BN + 2*cc;
#pragma unroll
            for (int nt = 0; nt < 8; ++nt){
                int gc = cb + 8*nt;
                if (gc   > gr0)   c[nt][0] = -1e30f;
                if (gc+1 > gr0)   c[nt][1] = -1e30f;
                if (gc   > gr0+8) c[nt][2] = -1e30f;
                if (gc+1 > gr0+8) c[nt][3] = -1e30f;
            }
        }

        __syncthreads();               // all warps done reading K(kt)
        if (kt + 1 < nkt){             // prefetch K(kt+1): hides under softmax+MMA2
            const char* gk2 = gk + (size_t)(kt + 1) * K_IMG;
#pragma unroll
            for (int i = 0; i < 9; ++i){
                int u = t + NT * i;
                if (u < K_UNITS) cpa16(sb + SM_K + u*16, gk2 + u*16);
            }
            CPA_COMMIT();
        }

        // ---- online softmax (log2 domain) ----
        float tm0 = -1e30f, tm1 = -1e30f;
#pragma unroll
        for (int nt = 0; nt < 8; ++nt){
            tm0 = fmaxf(tm0, fmaxf(c[nt][0], c[nt][1]));
            tm1 = fmaxf(tm1, fmaxf(c[nt][2], c[nt][3]));
        }
        tm0 = fmaxf(tm0, __shfl_xor_sync(0xffffffffu, tm0, 1));
        tm0 = fmaxf(tm0, __shfl_xor_sync(0xffffffffu, tm0, 2));
        tm1 = fmaxf(tm1, __shfl_xor_sync(0xffffffffu, tm1, 1));
        tm1 = fmaxf(tm1, __shfl_xor_sync(0xffffffffu, tm1, 2));
        float mn0 = fmaxf(m0, tm0), mn1 = fmaxf(m1, tm1);
        float al0 = ex2f_(m0 - mn0), al1 = ex2f_(m1 - mn1);
        m0 = mn0; m1 = mn1;

        uint32_t phi[16];
        float rs0 = 0.f, rs1 = 0.f;
#pragma unroll
        for (int nt = 0; nt < 8; ++nt){
            float p0 = ex2f_(c[nt][0]-mn0), p1 = ex2f_(c[nt][1]-mn0);
            float p2 = ex2f_(c[nt][2]-mn1), p3 = ex2f_(c[nt][3]-mn1);
            rs0 += p0 + p1; rs1 += p2 + p3;
            int base = (nt >> 1)*4 + (nt & 1)*2;
            phi[base]   = pkh(__float2half_rn(p0), __float2half_rn(p1));
            phi[base+1] = pkh(__float2half_rn(p2), __float2half_rn(p3));
        }
        rs0 += __shfl_xor_sync(0xffffffffu, rs0, 1);
        rs0 += __shfl_xor_sync(0xffffffffu, rs0, 2);
        rs1 += __shfl_xor_sync(0xffffffffu, rs1, 1);
        rs1 += __shfl_xor_sync(0xffffffffu, rs1, 2);
        l0 = l0*al0 + rs0; l1 = l1*al1 + rs1;

#pragma unroll
        for (int i = 0; i < 16; ++i){
            o[i][0] *= al0; o[i][1] *= al0; o[i][2] *= al1; o[i][3] *= al1;
        }

        CPA_WAIT(1);                   // V(kt) ready (K(kt+1) may fly)
        __syncthreads();

        // ---- MMA2: O += P V (fp16; P 1-term, V hi/lo) ----
#pragma unroll
        for (int kkp = 0; kkp < 4; ++kkp){
            uint32_t pa0 = phi[4*kkp], pa1 = phi[4*kkp+1],
                     pa2 = phi[4*kkp+2], pa3 = phi[4*kkp+3];
#pragma unroll
            for (int nt2 = 0; nt2 < 16; ++nt2){
                uint4 B = *(const uint4*)(sm + vfrag + nt2*(8*RS_V) + kkp*64);
                uint32_t b0h, b0l, b1h, b1l;
                if (nt2 & 1){ b0h = B.z; b0l = B.w; b1h = B.x; b1l = B.y; }
                else        { b0h = B.x; b0l = B.y; b1h = B.z; b1l = B.w; }
                mma_f16(o[nt2], pa0,pa1,pa2,pa3, b0h, b1h);   // P * Vhi
                mma_f16(o[nt2], pa0,pa1,pa2,pa3, b0l, b1l);   // P * Vlo
            }
        }

        __syncthreads();               // all warps done reading V(kt)
        if (kt + 1 < nkt){             // prefetch V(kt+1): hides under next MMA1
            const char* gv2 = gv + (size_t)(kt + 1) * V_IMG;
#pragma unroll
            for (int i = 0; i < 20; ++i){
                int u = t + NT * i;
                cpa16(sb + SM_V + u*16, gv2 + u*16);
            }
            CPA_COMMIT();
        }
    }

    // ---- epilogue ----
    float inv0 = 1.f / l0, inv1 = 1.f / l1;
    int r0 = qt*BM + 16*w + r3;
    float* po = out + ((size_t)h * S_LEN + r0) * DH + 2*cc;
#pragma unroll
    for (int nt2 = 0; nt2 < 16; ++nt2){
        *(float2*)(po + 8*nt2)        = make_float2(o[nt2][0]*inv0, o[nt2][1]*inv0);
        *(float2*)(po + 8*DH + 8*nt2) = make_float2(o[nt2][2]*inv1, o[nt2][3]*inv1);
    }
    if (cc == 0){
        const float LN2 = 0.6931471805599453f;
        size_t s0 = ((size_t)h * S_LEN + r0) * 8;
        size_t s1 = s0 + 64;   // row + 8
        float mn0 = m0 * LN2, mn1 = m1 * LN2;
        float4 mv0 = make_float4(mn0, mn0, mn0, mn0);
        float4 mv1 = make_float4(mn1, mn1, mn1, mn1);
        float4 lv0 = make_float4(l0, l0, l0, l0);
        float4 lv1 = make_float4(l1, l1, l1, l1);
        *(float4*)(omax + s0) = mv0; *(float4*)(omax + s0 + 4) = mv0;
        *(float4*)(omax + s1) = mv1; *(float4*)(omax + s1 + 4) = mv1;
        *(float4*)(osum + s0) = lv0; *(float4*)(osum + s0 + 4) = lv0;
        *(float4*)(osum + s1) = lv1; *(float4*)(osum + s1 + 4) = lv1;
    }
}

extern "C" void kernel_launch(void* const* d_in, const int* in_sizes, int n_in,
                              void* d_out, int out_size)
{
    const float* q = (const float*)d_in[0];
    const float* k = (const float*)d_in[1];
    const float* v = (const float*)d_in[2];

    float* out  = (float*)d_out;
    float* omax = out + (size_t)32 * 2048 * 128;
    float* osum = omax + (size_t)32 * 2048 * 8;

    dim3 pgrid(NTILE, NHEAD);
    fa_prep_kernel<<<pgrid, NT>>>(k, v);

    cudaFuncSetAttribute(fa_main_kernel,
                         cudaFuncAttributeMaxDynamicSharedMemorySize, SMEM_BYTES);
    dim3 grid(NTILE, NHEAD);
    fa_main_kernel<<<grid, NT, SMEM_BYTES>>>(q, out, omax, osum);
}

// round 9
// speedup vs baseline: 2.3121x; 1.2096x over previous
#include <cuda_runtime.h>
#include <cuda_fp16.h>
#include <cstdint>

// FlashAttentionScore B=2,N=16,S=2048,D=128 fp32 causal.
// prep: K,V -> fp16 single-plane fragment images (V transposed).
// main: cp.async early-prefetch + mma.sync fp16 (QK 1-term, PV 1-term).
// out layout: [out 32*2048*128][max x8][sum x8]

#define S_LEN 2048
#define DH    128
#define BM    64
#define BN    64
#define NT    128
#define NHEAD 32
#define NTILE 32

#define RS_QK 272           // 256B data + 16B pad (verified family)
#define RS_V  144           // 128B data + 16B pad (verified family, R3)
#define K_IMG (64*RS_QK)    // 17408
#define V_IMG (128*RS_V)    // 18432
#define K_UNITS (K_IMG/16)  // 1088
#define V_UNITS (V_IMG/16)  // 1152

#define SM_Q  0
#define SM_K  17408
#define SM_V  34816
#define SMEM_BYTES 53248    // 3 CTAs/SM

__device__ __align__(16) char g_kimg[NHEAD * NTILE * K_IMG];   // 17.8 MB
__device__ __align__(16) char g_vimg[NHEAD * NTILE * V_IMG];   // 18.9 MB

__device__ __forceinline__ float ex2f_(float x){
    float r; asm("ex2.approx.ftz.f32 %0, %1;" : "=f"(r) : "f"(x)); return r;
}
__device__ __forceinline__ uint32_t pkh(__half a, __half b){
    return (uint32_t)__half_as_ushort(a) | ((uint32_t)__half_as_ushort(b) << 16);
}
__device__ __forceinline__ void mma_f16(float c[4],
        uint32_t a0, uint32_t a1, uint32_t a2, uint32_t a3,
        uint32_t b0, uint32_t b1){
    asm volatile(
        "mma.sync.aligned.m16n8k16.row.col.f32.f16.f16.f32 "
        "{%0,%1,%2,%3}, {%4,%5,%6,%7}, {%8,%9}, {%0,%1,%2,%3};"
        : "+f"(c[0]), "+f"(c[1]), "+f"(c[2]), "+f"(c[3])
        : "r"(a0), "r"(a1), "r"(a2), "r"(a3), "r"(b0), "r"(b1));
}
__device__ __forceinline__ uint32_t smem_u32(const void* p){
    uint32_t a;
    asm("{ .reg .u64 t; cvta.to.shared.u64 t, %1; cvt.u32.u64 %0, t; }" : "=r"(a) : "l"(p));
    return a;
}
__device__ __forceinline__ void cpa16(uint32_t s, const char* g){
    asm volatile("cp.async.cg.shared.global [%0], [%1], 16;" :: "r"(s), "l"(g));
}
#define CPA_COMMIT() asm volatile("cp.async.commit_group;" ::: "memory")
#define CPA_WAIT(n)  asm volatile("cp.async.wait_group %0;" :: "n"(n) : "memory")

// Fragment image layout (verified): addr(row,kk,c) = row*RS + kk*32 + c*8
//   8B unit = [pair(8kk+c), pair(8kk+4+c)], pair w = k-elements {2w, 2w+1}
//   Q/K: row = q/key index, k-elements = d (8 kk-steps)
//   V:   row = d index,     k-elements = keys (4 kk-steps)

// ---------------- prep ----------------
__global__ void __launch_bounds__(NT)
fa_prep_kernel(const float* __restrict__ k, const float* __restrict__ v)
{
    const int t  = threadIdx.x;
    const int kt = blockIdx.x;
    const int h  = blockIdx.y;
    const int img = h * NTILE + kt;

    // ---- K tile -> fp16 image ----
    {
        const float* Kt = k + ((size_t)h * S_LEN + (size_t)kt * BN) * DH;
        char* kb = g_kimg + (size_t)img * K_IMG;
#pragma unroll
        for (int i = 0; i < 16; ++i){
            int idx = t + NT * i;            // row*32 + kk*4 + c
            int row = idx >> 5, kc = idx & 31;
            int kk = kc >> 2, c = kc & 3;
            int d0 = 16*kk + 2*c;
            float2 v0 = *(const float2*)(Kt + row * DH + d0);
            float2 v1 = *(const float2*)(Kt + row * DH + d0 + 8);
            uint2 u = make_uint2(pkh(__float2half_rn(v0.x), __float2half_rn(v0.y)),
                                 pkh(__float2half_rn(v1.x), __float2half_rn(v1.y)));
            *(uint2*)(kb + row * RS_QK + kk * 32 + c * 8) = u;
        }
    }
    // ---- V tile -> transposed fp16 image (row = d) ----
    {
        const float* Vt = v + ((size_t)h * S_LEN + (size_t)kt * BN) * DH;
        char* vb = g_vimg + (size_t)img * V_IMG;
        int m = t & 63, g = t >> 6;          // d pair = (2m, 2m+1); g: combo half
#pragma unroll
        for (int i = 0; i < 8; ++i){
            int j  = 8 * g + i;              // combo 0..15
            int kk = j >> 2, c = j & 3;
            int k0 = 16*kk + 2*c;
            float2 va = *(const float2*)(Vt + (k0    ) * DH + 2*m);
            float2 vb2= *(const float2*)(Vt + (k0 + 1) * DH + 2*m);
            float2 vc = *(const float2*)(Vt + (k0 + 8) * DH + 2*m);
            float2 vd = *(const float2*)(Vt + (k0 + 9) * DH + 2*m);
            // d = 2m
            *(uint2*)(vb + (2*m)   * RS_V + kk * 32 + c * 8) =
                make_uint2(pkh(__float2half_rn(va.x), __float2half_rn(vb2.x)),
                           pkh(__float2half_rn(vc.x), __float2half_rn(vd.x)));
            // d = 2m+1
            *(uint2*)(vb + (2*m+1) * RS_V + kk * 32 + c * 8) =
                make_uint2(pkh(__float2half_rn(va.y), __float2half_rn(vb2.y)),
                           pkh(__float2half_rn(vc.y), __float2half_rn(vd.y)));
        }
    }
}

// ---------------- main ----------------
__global__ void __launch_bounds__(NT, 3)
fa_main_kernel(const float* __restrict__ q, float* __restrict__ out,
               float* __restrict__ omax, float* __restrict__ osum)
{
    extern __shared__ char sm[];
    const int t = threadIdx.x;
    const int l = t & 31;
    const int w = t >> 5;
    const int h = blockIdx.y;
    const int qt = 31 - (int)blockIdx.x;   // big tiles first
    const int nkt = qt + 1;

    const uint32_t sb = smem_u32(sm);
    const char* gk = g_kimg + (size_t)h * NTILE * K_IMG;
    const char* gv = g_vimg + (size_t)h * NTILE * V_IMG;

    // ---- prologue: async K0,V0; Q converted inline ----
#pragma unroll
    for (int i = 0; i < 9; ++i){
        int u = t + NT * i;
        if (u < K_UNITS) cpa16(sb + SM_K + u*16, gk + u*16);
    }
    CPA_COMMIT();                      // group: K0
#pragma unroll
    for (int i = 0; i < 9; ++i){
        int u = t + NT * i;
        cpa16(sb + SM_V + u*16, gv + u*16);    // 128*9 = 1152 = V_UNITS
    }
    CPA_COMMIT();                      // group: V0

    const float QSCALE = 0.08838834764831845f * 1.4426950408889634f; // 1/sqrt(D)*log2e
    {
        const float* Qt = q + ((size_t)h * S_LEN + (size_t)qt * BM) * DH;
#pragma unroll
        for (int i = 0; i < 16; ++i){
            int idx = t + NT * i;
            int row = idx >> 5, kc = idx & 31;
            int kk = kc >> 2, c = kc & 3;
            int d0 = 16*kk + 2*c;
            float2 v0 = *(const float2*)(Qt + row * DH + d0);
            float2 v1 = *(const float2*)(Qt + row * DH + d0 + 8);
            uint2 u = make_uint2(pkh(__float2half_rn(v0.x * QSCALE),
                                     __float2half_rn(v0.y * QSCALE)),
                                 pkh(__float2half_rn(v1.x * QSCALE),
                                     __float2half_rn(v1.y * QSCALE)));
            *(uint2*)(sm + SM_Q + row * RS_QK + kk * 32 + c * 8) = u;
        }
    }

    float o[16][4];
#pragma unroll
    for (int i = 0; i < 16; ++i){ o[i][0]=o[i][1]=o[i][2]=o[i][3]=0.f; }
    float m0=-1e30f, m1=-1e30f, l0=0.f, l1=0.f;

    const int r3 = l >> 2, cc = l & 3;
    const uint32_t qa    = SM_Q + (uint32_t)(16*w + r3) * RS_QK + cc*8;
    const uint32_t kfrag = SM_K + (uint32_t)r3 * RS_QK + cc*8;
    const uint32_t vfrag = SM_V + (uint32_t)r3 * RS_V + cc*8;

#pragma unroll 1
    for (int kt = 0; kt < nkt; ++kt){
        CPA_WAIT(1);                   // K(kt) ready
        __syncthreads();

        // ---- MMA1: S = Q K^T (fp16 1-term) ----
        float c[8][4];
#pragma unroll
        for (int i = 0; i < 8; ++i){ c[i][0]=c[i][1]=c[i][2]=c[i][3]=0.f; }
#pragma unroll
        for (int kk = 0; kk < 8; ++kk){
            uint2 A0 = *(const uint2*)(sm + qa + kk*32);             // row r
            uint2 A1 = *(const uint2*)(sm + qa + kk*32 + 8*RS_QK);   // row r+8
#pragma unroll
            for (int nt = 0; nt < 8; ++nt){
                uint2 B = *(const uint2*)(sm + kfrag + nt*(8*RS_QK) + kk*32);
                mma_f16(c[nt], A0.x, A1.x, A0.y, A1.y, B.x, B.y);
            }
        }

        // ---- causal mask (diagonal tile only) ----
        if (kt == qt){
            int gr0 = qt*BM + 16*w + r3;
            int cb  = kt*BN + 2*cc;
#pragma unroll
            for (int nt = 0; nt < 8; ++nt){
                int gc = cb + 8*nt;
                if (gc   > gr0)   c[nt][0] = -1e30f;
                if (gc+1 > gr0)   c[nt][1] = -1e30f;
                if (gc   > gr0+8) c[nt][2] = -1e30f;
                if (gc+1 > gr0+8) c[nt][3] = -1e30f;
            }
        }

        __syncthreads();               // all warps done reading K(kt)
        if (kt + 1 < nkt){             // prefetch K(kt+1): hides under softmax+MMA2
            const char* gk2 = gk + (size_t)(kt + 1) * K_IMG;
#pragma unroll
            for (int i = 0; i < 9; ++i){
                int u = t + NT * i;
                if (u < K_UNITS) cpa16(sb + SM_K + u*16, gk2 + u*16);
            }
            CPA_COMMIT();
        }

        // ---- online softmax (log2 domain) ----
        float tm0 = -1e30f, tm1 = -1e30f;
#pragma unroll
        for (int nt = 0; nt < 8; ++nt){
            tm0 = fmaxf(tm0, fmaxf(c[nt][0], c[nt][1]));
            tm1 = fmaxf(tm1, fmaxf(c[nt][2], c[nt][3]));
        }
        tm0 = fmaxf(tm0, __shfl_xor_sync(0xffffffffu, tm0, 1));
        tm0 = fmaxf(tm0, __shfl_xor_sync(0xffffffffu, tm0, 2));
        tm1 = fmaxf(tm1, __shfl_xor_sync(0xffffffffu, tm1, 1));
        tm1 = fmaxf(tm1, __shfl_xor_sync(0xffffffffu, tm1, 2));
        float mn0 = fmaxf(m0, tm0), mn1 = fmaxf(m1, tm1);
        float al0 = ex2f_(m0 - mn0), al1 = ex2f_(m1 - mn1);
        m0 = mn0; m1 = mn1;

        uint32_t phi[16];
        float rs0 = 0.f, rs1 = 0.f;
#pragma unroll
        for (int nt = 0; nt < 8; ++nt){
            float p0 = ex2f_(c[nt][0]-mn0), p1 = ex2f_(c[nt][1]-mn0);
            float p2 = ex2f_(c[nt][2]-mn1), p3 = ex2f_(c[nt][3]-mn1);
            rs0 += p0 + p1; rs1 += p2 + p3;
            int base = (nt >> 1)*4 + (nt & 1)*2;
            phi[base]   = pkh(__float2half_rn(p0), __float2half_rn(p1));
            phi[base+1] = pkh(__float2half_rn(p2), __float2half_rn(p3));
        }
        rs0 += __shfl_xor_sync(0xffffffffu, rs0, 1);
        rs0 += __shfl_xor_sync(0xffffffffu, rs0, 2);
        rs1 += __shfl_xor_sync(0xffffffffu, rs1, 1);
        rs1 += __shfl_xor_sync(0xffffffffu, rs1, 2);
        l0 = l0*al0 + rs0; l1 = l1*al1 + rs1;

#pragma unroll
        for (int i = 0; i < 16; ++i){
            o[i][0] *= al0; o[i][1] *= al0; o[i][2] *= al1; o[i][3] *= al1;
        }

        CPA_WAIT(1);                   // V(kt) ready (K(kt+1) may fly)
        __syncthreads();

        // ---- MMA2: O += P V (fp16 1-term; V image row = d) ----
#pragma unroll
        for (int kkp = 0; kkp < 4; ++kkp){
            uint32_t pa0 = phi[4*kkp], pa1 = phi[4*kkp+1],
                     pa2 = phi[4*kkp+2], pa3 = phi[4*kkp+3];
#pragma unroll
            for (int nt2 = 0; nt2 < 16; ++nt2){
                uint2 B = *(const uint2*)(sm + vfrag + nt2*(8*RS_V) + kkp*32);
                mma_f16(o[nt2], pa0,pa1,pa2,pa3, B.x, B.y);
            }
        }

        __syncthreads();               // all warps done reading V(kt)
        if (kt + 1 < nkt){             // prefetch V(kt+1): hides under next MMA1
            const char* gv2 = gv + (size_t)(kt + 1) * V_IMG;
#pragma unroll
            for (int i = 0; i < 9; ++i){
                int u = t + NT * i;
                cpa16(sb + SM_V + u*16, gv2 + u*16);
            }
            CPA_COMMIT();
        }
    }

    // ---- epilogue ----
    float inv0 = 1.f / l0, inv1 = 1.f / l1;
    int r0 = qt*BM + 16*w + r3;
    float* po = out + ((size_t)h * S_LEN + r0) * DH + 2*cc;
#pragma unroll
    for (int nt2 = 0; nt2 < 16; ++nt2){
        *(float2*)(po + 8*nt2)        = make_float2(o[nt2][0]*inv0, o[nt2][1]*inv0);
        *(float2*)(po + 8*DH + 8*nt2) = make_float2(o[nt2][2]*inv1, o[nt2][3]*inv1);
    }
    if (cc == 0){
        const float LN2 = 0.6931471805599453f;
        size_t s0 = ((size_t)h * S_LEN + r0) * 8;
        size_t s1 = s0 + 64;   // row + 8
        float mn0 = m0 * LN2, mn1 = m1 * LN2;
        float4 mv0 = make_float4(mn0, mn0, mn0, mn0);
        float4 mv1 = make_float4(mn1, mn1, mn1, mn1);
        float4 lv0 = make_float4(l0, l0, l0, l0);
        float4 lv1 = make_float4(l1, l1, l1, l1);
        *(float4*)(omax + s0) = mv0; *(float4*)(omax + s0 + 4) = mv0;
        *(float4*)(omax + s1) = mv1; *(float4*)(omax + s1 + 4) = mv1;
        *(float4*)(osum + s0) = lv0; *(float4*)(osum + s0 + 4) = lv0;
        *(float4*)(osum + s1) = lv1; *(float4*)(osum + s1 + 4) = lv1;
    }
}

extern "C" void kernel_launch(void* const* d_in, const int* in_sizes, int n_in,
                              void* d_out, int out_size)
{
    const float* q = (const float*)d_in[0];
    const float* k = (const float*)d_in[1];
    const float* v = (const float*)d_in[2];

    float* out  = (float*)d_out;
    float* omax = out + (size_t)32 * 2048 * 128;
    float* osum = omax + (size_t)32 * 2048 * 8;

    dim3 pgrid(NTILE, NHEAD);
    fa_prep_kernel<<<pgrid, NT>>>(k, v);

    cudaFuncSetAttribute(fa_main_kernel,
                         cudaFuncAttributeMaxDynamicSharedMemorySize, SMEM_BYTES);
    dim3 grid(NTILE, NHEAD);
    fa_main_kernel<<<grid, NT, SMEM_BYTES>>>(q, out, omax, osum);
}

// round 11
// speedup vs baseline: 3.0854x; 1.3345x over previous
#include <cuda_runtime.h>
#include <cuda_fp16.h>
#include <cstdint>

// FlashAttentionScore B=2,N=16,S=2048,D=128 fp32 causal.
// prep: K,V -> fp16 single-plane fragment images (V transposed).
// main: cp.async early-prefetch + mma.sync fp16 (QK 1-term, PV 1-term).
// Row strides 288/160 (≡8 mod 32 words): conflict-free LDS.64 fragment reads.
// FIX vs R10: final iteration must wait_group 0 before MMA2 (no K-prefetch
// group behind V -> wait_group 1 returned without completing V: race).
// out layout: [out 32*2048*128][max x8][sum x8]

#define S_LEN 2048
#define DH    128
#define BM    64
#define BN    64
#define NT    128
#define NHEAD 32
#define NTILE 32

#define RS_QK 288           // 256B data + 32B pad  (72 words ≡ 8 mod 32)
#define RS_V  160           // 128B data + 32B pad  (40 words ≡ 8 mod 32)
#define K_IMG (64*RS_QK)    // 18432
#define V_IMG (128*RS_V)    // 20480
#define K_UNITS (K_IMG/16)  // 1152 = 128*9
#define V_UNITS (V_IMG/16)  // 1280 = 128*10

#define SM_Q  0
#define SM_K  18432
#define SM_V  36864
#define SMEM_BYTES 57344    // 3 CTAs/SM

__device__ __align__(16) char g_kimg[NHEAD * NTILE * K_IMG];   // 18.9 MB
__device__ __align__(16) char g_vimg[NHEAD * NTILE * V_IMG];   // 21.0 MB

__device__ __forceinline__ float ex2f_(float x){
    float r; asm("ex2.approx.ftz.f32 %0, %1;" : "=f"(r) : "f"(x)); return r;
}
__device__ __forceinline__ uint32_t pkh(__half a, __half b){
    return (uint32_t)__half_as_ushort(a) | ((uint32_t)__half_as_ushort(b) << 16);
}
__device__ __forceinline__ void mma_f16(float c[4],
        uint32_t a0, uint32_t a1, uint32_t a2, uint32_t a3,
        uint32_t b0, uint32_t b1){
    asm volatile(
        "mma.sync.aligned.m16n8k16.row.col.f32.f16.f16.f32 "
        "{%0,%1,%2,%3}, {%4,%5,%6,%7}, {%8,%9}, {%0,%1,%2,%3};"
        : "+f"(c[0]), "+f"(c[1]), "+f"(c[2]), "+f"(c[3])
        : "r"(a0), "r"(a1), "r"(a2), "r"(a3), "r"(b0), "r"(b1));
}
__device__ __forceinline__ uint32_t smem_u32(const void* p){
    uint32_t a;
    asm("{ .reg .u64 t; cvta.to.shared.u64 t, %1; cvt.u32.u64 %0, t; }" : "=r"(a) : "l"(p));
    return a;
}
__device__ __forceinline__ void cpa16(uint32_t s, const char* g){
    asm volatile("cp.async.cg.shared.global [%0], [%1], 16;" :: "r"(s), "l"(g));
}
#define CPA_COMMIT() asm volatile("cp.async.commit_group;" ::: "memory")
#define CPA_WAIT(n)  asm volatile("cp.async.wait_group %0;" :: "n"(n) : "memory")

// Fragment image layout: addr(row,kk,c) = row*RS + kk*32 + c*8
//   8B unit = [pair(8kk+c), pair(8kk+4+c)], pair w = k-elements {2w, 2w+1}
//   Q/K: row = q/key index (8 kk-steps);  V: row = d index (4 kk-steps)

// ---------------- prep ----------------
__global__ void __launch_bounds__(NT)
fa_prep_kernel(const float* __restrict__ k, const float* __restrict__ v)
{
    const int t  = threadIdx.x;
    const int kt = blockIdx.x;
    const int h  = blockIdx.y;
    const int img = h * NTILE + kt;

    // ---- K tile -> fp16 image ----
    {
        const float* Kt = k + ((size_t)h * S_LEN + (size_t)kt * BN) * DH;
        char* kb = g_kimg + (size_t)img * K_IMG;
#pragma unroll
        for (int i = 0; i < 16; ++i){
            int idx = t + NT * i;            // row*32 + kk*4 + c
            int row = idx >> 5, kc = idx & 31;
            int kk = kc >> 2, c = kc & 3;
            int d0 = 16*kk + 2*c;
            float2 v0 = *(const float2*)(Kt + row * DH + d0);
            float2 v1 = *(const float2*)(Kt + row * DH + d0 + 8);
            uint2 u = make_uint2(pkh(__float2half_rn(v0.x), __float2half_rn(v0.y)),
                                 pkh(__float2half_rn(v1.x), __float2half_rn(v1.y)));
            *(uint2*)(kb + row * RS_QK + kk * 32 + c * 8) = u;
        }
    }
    // ---- V tile -> transposed fp16 image (row = d) ----
    {
        const float* Vt = v + ((size_t)h * S_LEN + (size_t)kt * BN) * DH;
        char* vb = g_vimg + (size_t)img * V_IMG;
        int m = t & 63, g = t >> 6;
#pragma unroll
        for (int i = 0; i < 8; ++i){
            int j  = 8 * g + i;              // combo 0..15
            int kk = j >> 2, c = j & 3;
            int k0 = 16*kk + 2*c;
            float2 va = *(const float2*)(Vt + (k0    ) * DH + 2*m);
            float2 vb2= *(const float2*)(Vt + (k0 + 1) * DH + 2*m);
            float2 vc = *(const float2*)(Vt + (k0 + 8) * DH + 2*m);
            float2 vd = *(const float2*)(Vt + (k0 + 9) * DH + 2*m);
            *(uint2*)(vb + (2*m)   * RS_V + kk * 32 + c * 8) =
                make_uint2(pkh(__float2half_rn(va.x), __float2half_rn(vb2.x)),
                           pkh(__float2half_rn(vc.x), __float2half_rn(vd.x)));
            *(uint2*)(vb + (2*m+1) * RS_V + kk * 32 + c * 8) =
                make_uint2(pkh(__float2half_rn(va.y), __float2half_rn(vb2.y)),
                           pkh(__float2half_rn(vc.y), __float2half_rn(vd.y)));
        }
    }
}

// ---------------- main ----------------
__global__ void __launch_bounds__(NT, 3)
fa_main_kernel(const float* __restrict__ q, float* __restrict__ out,
               float* __restrict__ omax, float* __restrict__ osum)
{
    extern __shared__ char sm[];
    const int t = threadIdx.x;
    const int l = t & 31;
    const int w = t >> 5;
    const int h = blockIdx.y;
    const int qt = 31 - (int)blockIdx.x;   // big tiles first
    const int nkt = qt + 1;

    const uint32_t sb = smem_u32(sm);
    const char* gk = g_kimg + (size_t)h * NTILE * K_IMG;
    const char* gv = g_vimg + (size_t)h * NTILE * V_IMG;

    // ---- prologue: async K0,V0; Q converted inline ----
#pragma unroll
    for (int i = 0; i < 9; ++i){
        int u = t + NT * i;
        cpa16(sb + SM_K + u*16, gk + u*16);      // 1152 units
    }
    CPA_COMMIT();                      // group: K0
#pragma unroll
    for (int i = 0; i < 10; ++i){
        int u = t + NT * i;
        cpa16(sb + SM_V + u*16, gv + u*16);      // 1280 units
    }
    CPA_COMMIT();                      // group: V0

    const float QSCALE = 0.08838834764831845f * 1.4426950408889634f; // 1/sqrt(D)*log2e
    {
        const float* Qt = q + ((size_t)h * S_LEN + (size_t)qt * BM) * DH;
#pragma unroll
        for (int i = 0; i < 16; ++i){
            int idx = t + NT * i;
            int row = idx >> 5, kc = idx & 31;
            int kk = kc >> 2, c = kc & 3;
            int d0 = 16*kk + 2*c;
            float2 v0 = *(const float2*)(Qt + row * DH + d0);
            float2 v1 = *(const float2*)(Qt + row * DH + d0 + 8);
            uint2 u = make_uint2(pkh(__float2half_rn(v0.x * QSCALE),
                                     __float2half_rn(v0.y * QSCALE)),
                                 pkh(__float2half_rn(v1.x * QSCALE),
                                     __float2half_rn(v1.y * QSCALE)));
            *(uint2*)(sm + SM_Q + row * RS_QK + kk * 32 + c * 8) = u;
        }
    }

    float o[16][4];
#pragma unroll
    for (int i = 0; i < 16; ++i){ o[i][0]=o[i][1]=o[i][2]=o[i][3]=0.f; }
    float m0=-1e30f, m1=-1e30f, l0=0.f, l1=0.f;

    const int r3 = l >> 2, cc = l & 3;
    const uint32_t qa    = SM_Q + (uint32_t)(16*w + r3) * RS_QK + cc*8;
    const uint32_t kfrag = SM_K + (uint32_t)r3 * RS_QK + cc*8;
    const uint32_t vfrag = SM_V + (uint32_t)r3 * RS_V + cc*8;

#pragma unroll 1
    for (int kt = 0; kt < nkt; ++kt){
        CPA_WAIT(1);                   // completes K(kt): oldest of {K(kt), V(kt)}
        __syncthreads();

        // ---- MMA1: S = Q K^T (fp16 1-term) ----
        float c[8][4];
#pragma unroll
        for (int i = 0; i < 8; ++i){ c[i][0]=c[i][1]=c[i][2]=c[i][3]=0.f; }
#pragma unroll
        for (int kk = 0; kk < 8; ++kk){
            uint2 A0 = *(const uint2*)(sm + qa + kk*32);             // row r
            uint2 A1 = *(const uint2*)(sm + qa + kk*32 + 8*RS_QK);   // row r+8
#pragma unroll
            for (int nt = 0; nt < 8; ++nt){
                uint2 B = *(const uint2*)(sm + kfrag + nt*(8*RS_QK) + kk*32);
                mma_f16(c[nt], A0.x, A1.x, A0.y, A1.y, B.x, B.y);
            }
        }

        // ---- causal mask (diagonal tile only) ----
        if (kt == qt){
            int gr0 = qt*BM + 16*w + r3;
            int cb  = kt*BN + 2*cc;
#pragma unroll
            for (int nt = 0; nt < 8; ++nt){
                int gc = cb + 8*nt;
                if (gc   > gr0)   c[nt][0] = -1e30f;
                if (gc+1 > gr0)   c[nt][1] = -1e30f;
                if (gc   > gr0+8) c[nt][2] = -1e30f;
                if (gc+1 > gr0+8) c[nt][3] = -1e30f;
            }
        }

        __syncthreads();               // all warps done reading K(kt)
        if (kt + 1 < nkt){             // prefetch K(kt+1): hides under softmax+MMA2
            const char* gk2 = gk + (size_t)(kt + 1) * K_IMG;
#pragma unroll
            for (int i = 0; i < 9; ++i){
                int u = t + NT * i;
                cpa16(sb + SM_K + u*16, gk2 + u*16);
            }
            CPA_COMMIT();
        }

        // ---- online softmax (log2 domain) ----
        float tm0 = -1e30f, tm1 = -1e30f;
#pragma unroll
        for (int nt = 0; nt < 8; ++nt){
            tm0 = fmaxf(tm0, fmaxf(c[nt][0], c[nt][1]));
            tm1 = fmaxf(tm1, fmaxf(c[nt][2], c[nt][3]));
        }
        tm0 = fmaxf(tm0, __shfl_xor_sync(0xffffffffu, tm0, 1));
        tm0 = fmaxf(tm0, __shfl_xor_sync(0xffffffffu, tm0, 2));
        tm1 = fmaxf(tm1, __shfl_xor_sync(0xffffffffu, tm1, 1));
        tm1 = fmaxf(tm1, __shfl_xor_sync(0xffffffffu, tm1, 2));
        float mn0 = fmaxf(m0, tm0), mn1 = fmaxf(m1, tm1);
        float al0 = ex2f_(m0 - mn0), al1 = ex2f_(m1 - mn1);
        m0 = mn0; m1 = mn1;

        uint32_t phi[16];
        float rs0 = 0.f, rs1 = 0.f;
#pragma unroll
        for (int nt = 0; nt < 8; ++nt){
            float p0 = ex2f_(c[nt][0]-mn0), p1 = ex2f_(c[nt][1]-mn0);
            float p2 = ex2f_(c[nt][2]-mn1), p3 = ex2f_(c[nt][3]-mn1);
            rs0 += p0 + p1; rs1 += p2 + p3;
            int base = (nt >> 1)*4 + (nt & 1)*2;
            phi[base]   = pkh(__float2half_rn(p0), __float2half_rn(p1));
            phi[base+1] = pkh(__float2half_rn(p2), __float2half_rn(p3));
        }
        rs0 += __shfl_xor_sync(0xffffffffu, rs0, 1);
        rs0 += __shfl_xor_sync(0xffffffffu, rs0, 2);
        rs1 += __shfl_xor_sync(0xffffffffu, rs1, 1);
        rs1 += __shfl_xor_sync(0xffffffffu, rs1, 2);
        l0 = l0*al0 + rs0; l1 = l1*al1 + rs1;

#pragma unroll
        for (int i = 0; i < 16; ++i){
            o[i][0] *= al0; o[i][1] *= al0; o[i][2] *= al1; o[i][3] *= al1;
        }

        // V(kt) must be COMPLETE before MMA2.
        // Mid-loop: pending = {V(kt), K(kt+1)} -> wait(1) completes V(kt).
        // Last iter: pending = {V(kt)} only -> wait(1) would return without
        // completing it (the R10 race). Use wait(0) there.
        if (kt + 1 < nkt){ CPA_WAIT(1); } else { CPA_WAIT(0); }
        __syncthreads();

        // ---- MMA2: O += P V (fp16 1-term; V image row = d) ----
#pragma unroll
        for (int kkp = 0; kkp < 4; ++kkp){
            uint32_t pa0 = phi[4*kkp], pa1 = phi[4*kkp+1],
                     pa2 = phi[4*kkp+2], pa3 = phi[4*kkp+3];
#pragma unroll
            for (int nt2 = 0; nt2 < 16; ++nt2){
                uint2 B = *(const uint2*)(sm + vfrag + nt2*(8*RS_V) + kkp*32);
                mma_f16(o[nt2], pa0,pa1,pa2,pa3, B.x, B.y);
            }
        }

        __syncthreads();               // all warps done reading V(kt)
        if (kt + 1 < nkt){             // prefetch V(kt+1): hides under next MMA1
            const char* gv2 = gv + (size_t)(kt + 1) * V_IMG;
#pragma unroll
            for (int i = 0; i < 10; ++i){
                int u = t + NT * i;
                cpa16(sb + SM_V + u*16, gv2 + u*16);
            }
            CPA_COMMIT();
        }
    }

    // ---- epilogue ----
    float inv0 = 1.f / l0, inv1 = 1.f / l1;
    int r0 = qt*BM + 16*w + r3;
    float* po = out + ((size_t)h * S_LEN + r0) * DH + 2*cc;
#pragma unroll
    for (int nt2 = 0; nt2 < 16; ++nt2){
        *(float2*)(po + 8*nt2)        = make_float2(o[nt2][0]*inv0, o[nt2][1]*inv0);
        *(float2*)(po + 8*DH + 8*nt2) = make_float2(o[nt2][2]*inv1, o[nt2][3]*inv1);
    }
    if (cc == 0){
        const float LN2 = 0.6931471805599453f;
        size_t s0 = ((size_t)h * S_LEN + r0) * 8;
        size_t s1 = s0 + 64;   // row + 8
        float mn0 = m0 * LN2, mn1 = m1 * LN2;
        float4 mv0 = make_float4(mn0, mn0, mn0, mn0);
        float4 mv1 = make_float4(mn1, mn1, mn1, mn1);
        float4 lv0 = make_float4(l0, l0, l0, l0);
        float4 lv1 = make_float4(l1, l1, l1, l1);
        *(float4*)(omax + s0) = mv0; *(float4*)(omax + s0 + 4) = mv0;
        *(float4*)(omax + s1) = mv1; *(float4*)(omax + s1 + 4) = mv1;
        *(float4*)(osum + s0) = lv0; *(float4*)(osum + s0 + 4) = lv0;
        *(float4*)(osum + s1) = lv1; *(float4*)(osum + s1 + 4) = lv1;
    }
}

extern "C" void kernel_launch(void* const* d_in, const int* in_sizes, int n_in,
                              void* d_out, int out_size)
{
    const float* q = (const float*)d_in[0];
    const float* k = (const float*)d_in[1];
    const float* v = (const float*)d_in[2];

    float* out  = (float*)d_out;
    float* omax = out + (size_t)32 * 2048 * 128;
    float* osum = omax + (size_t)32 * 2048 * 8;

    dim3 pgrid(NTILE, NHEAD);
    fa_prep_kernel<<<pgrid, NT>>>(k, v);

    cudaFuncSetAttribute(fa_main_kernel,
                         cudaFuncAttributeMaxDynamicSharedMemorySize, SMEM_BYTES);
    dim3 grid(NTILE, NHEAD);
    fa_main_kernel<<<grid, NT, SMEM_BYTES>>>(q, out, omax, osum);
}